// round 10
// baseline (speedup 1.0000x reference)
#include <cuda_runtime.h>

typedef unsigned long long u64;

#define DN 50000
#define DE 800000
#define DK 40000
#define NBLK 49   // ceil(DN/1024) for the kept-node compaction

// ---------------- scratch layout (single __device__ blob) ----------------
static constexpr size_t OFF_XA   = 0;                               // DN*128 (gather-raw out, reused)
static constexpr size_t OFF_HA   = OFF_XA  + (size_t)DN*128*4;      // DN*128 conv out
static constexpr size_t OFF_HP   = OFF_HA  + (size_t)DN*128*4;      // DK*128 pooled feats
static constexpr size_t OFF_GM   = OFF_HP  + (size_t)DK*128*4;      // DK*64 gemm out
static constexpr size_t OFF_T2   = OFF_GM  + (size_t)DK*64*4;       // DK*64 conv2 out
static constexpr size_t OFF_DIS1 = OFF_T2  + (size_t)DK*64*4;       // DN
static constexpr size_t OFF_DIS2 = OFF_DIS1 + (size_t)DN*4;         // DK
static constexpr size_t OFF_DEG1 = OFF_DIS2 + (size_t)DK*4;         // DN
static constexpr size_t OFF_DEG2 = OFF_DEG1 + (size_t)DN*4;         // DK
static constexpr size_t OFF_RP1  = OFF_DEG2 + (size_t)DK*4;         // DN+1
static constexpr size_t OFF_CUR1 = OFF_RP1  + (size_t)(DN+1)*4;     // DN
static constexpr size_t OFF_RP2  = OFF_CUR1 + (size_t)DN*4;         // DK+1
static constexpr size_t OFF_CUR2 = OFF_RP2  + (size_t)(DK+1)*4;     // DK (unused scratch for scanwrite)
static constexpr size_t OFF_CSR1 = OFF_CUR2 + (size_t)DK*4;         // DE
static constexpr size_t OFF_CSR2 = OFF_CSR1 + (size_t)DE*4;         // DE
static constexpr size_t OFF_SCORE= OFF_CSR2 + (size_t)DE*4;         // DN
static constexpr size_t OFF_KEY  = OFF_SCORE+ (size_t)DN*4;         // DN u64
static constexpr size_t OFF_CAND = OFF_KEY  + (size_t)DN*8;         // DN u64
static constexpr size_t OFF_NEW  = OFF_CAND + (size_t)DN*8;         // DN
static constexpr size_t OFF_BINS = OFF_NEW  + (size_t)DN*4;
static constexpr size_t OFF_BSUM = OFF_BINS + 256*4;                // 64
static constexpr size_t OFF_PFX  = OFF_BSUM + 64*4;
static constexpr size_t OFF_CCNT = OFF_PFX  + 8;
static constexpr size_t OFF_ACC  = OFF_CCNT + 4;
static constexpr size_t TOTAL_BYTES = OFF_ACC + 64*4;

__device__ __align__(256) unsigned char g_scratch[TOTAL_BYTES];

// ---------------- init: reset all per-replay state in one launch ------------
__global__ void init_kernel(int* deg1, int* bins, float* acc, int* ccnt){
    int i = blockIdx.x*blockDim.x + threadIdx.x;
    if (i < DN)  deg1[i] = 0;
    if (i < 256) bins[i] = 0;
    if (i < 64)  acc[i]  = 0.f;
    if (i == 0)  *ccnt = 0;
}

// ---- GEMM: transposed-X smem, 4x4 register tile, broadcast x-reads ---------
// Y = X@W (+bias, relu if EPI). sX stored as sX[k*PITCH + r] (PITCH=ROWS+4).
// Compute: per k, 1 LDS128 x (warp-broadcast) + 1 LDS128 w + 16 FFMA.
template<int KIN, int KOUT, int ROWS, bool EPI>
__global__ void gemm_tb(const float* __restrict__ X, const float* __restrict__ W,
                        const float* __restrict__ bias, float* __restrict__ Y, int M){
    constexpr int PITCH = ROWS + 4;
    constexpr int CG = KOUT/4;
    constexpr int RG = ROWS/4;
    extern __shared__ float sm[];
    float* sW = sm;                   // KIN*KOUT
    float* sX = sm + KIN*KOUT;        // KIN*PITCH (transposed)
    const int tid = threadIdx.x;
    for (int i = tid; i < KIN*KOUT/4; i += blockDim.x)
        ((float4*)sW)[i] = ((const float4*)W)[i];
    const int row0 = blockIdx.x * ROWS;
    for (int i = tid; i < ROWS*(KIN/4); i += blockDim.x){
        int r  = i / (KIN/4);
        int c4 = i % (KIN/4);
        int gr = row0 + r;
        float4 v = (gr < M) ? ((const float4*)X)[(size_t)gr*(KIN/4) + c4]
                            : make_float4(0.f,0.f,0.f,0.f);
        sX[(4*c4+0)*PITCH + r] = v.x;
        sX[(4*c4+1)*PITCH + r] = v.y;
        sX[(4*c4+2)*PITCH + r] = v.z;
        sX[(4*c4+3)*PITCH + r] = v.w;
    }
    __syncthreads();
    const float4* w4 = (const float4*)sW;
    for (int it = tid; it < RG*CG; it += blockDim.x){
        int rg = it / CG, cg = it % CG;
        int r0 = rg*4;
        float4 a0 = make_float4(0,0,0,0), a1 = a0, a2 = a0, a3 = a0;
        #pragma unroll 8
        for (int k = 0; k < KIN; k++){
            float4 w  = w4[k*CG + cg];
            float4 xv = *(const float4*)&sX[k*PITCH + r0];
            a0.x += xv.x*w.x; a0.y += xv.x*w.y; a0.z += xv.x*w.z; a0.w += xv.x*w.w;
            a1.x += xv.y*w.x; a1.y += xv.y*w.y; a1.z += xv.y*w.z; a1.w += xv.y*w.w;
            a2.x += xv.z*w.x; a2.y += xv.z*w.y; a2.z += xv.z*w.z; a2.w += xv.z*w.w;
            a3.x += xv.w*w.x; a3.y += xv.w*w.y; a3.z += xv.w*w.z; a3.w += xv.w*w.w;
        }
        if (EPI){
            float4 b = ((const float4*)bias)[cg];
            a0.x = fmaxf(a0.x+b.x, 0.f); a0.y = fmaxf(a0.y+b.y, 0.f);
            a0.z = fmaxf(a0.z+b.z, 0.f); a0.w = fmaxf(a0.w+b.w, 0.f);
            a1.x = fmaxf(a1.x+b.x, 0.f); a1.y = fmaxf(a1.y+b.y, 0.f);
            a1.z = fmaxf(a1.z+b.z, 0.f); a1.w = fmaxf(a1.w+b.w, 0.f);
            a2.x = fmaxf(a2.x+b.x, 0.f); a2.y = fmaxf(a2.y+b.y, 0.f);
            a2.z = fmaxf(a2.z+b.z, 0.f); a2.w = fmaxf(a2.w+b.w, 0.f);
            a3.x = fmaxf(a3.x+b.x, 0.f); a3.y = fmaxf(a3.y+b.y, 0.f);
            a3.z = fmaxf(a3.z+b.z, 0.f); a3.w = fmaxf(a3.w+b.w, 0.f);
        }
        float4* yp = (float4*)Y;
        int gr = row0 + r0;
        if (gr+0 < M) yp[(size_t)(gr+0)*CG + cg] = a0;
        if (gr+1 < M) yp[(size_t)(gr+1)*CG + cg] = a1;
        if (gr+2 < M) yp[(size_t)(gr+2)*CG + cg] = a2;
        if (gr+3 < M) yp[(size_t)(gr+3)*CG + cg] = a3;
    }
}

// ---------------- degree histogram ----------------
__global__ void deg_kernel(const int* __restrict__ dst, int* __restrict__ deg){
    int e = blockIdx.x*blockDim.x + threadIdx.x;
    if (e < DE) atomicAdd(&deg[dst[e]], 1);
}

// ---------------- 2-launch device-wide scan ----------------
__global__ void blocksum_kernel(const int* __restrict__ deg, int* __restrict__ bsums, int M){
    __shared__ int sh[256];
    int tid = threadIdx.x;
    int base = blockIdx.x * 1024;
    int s = 0;
    #pragma unroll
    for (int j = 0; j < 4; j++){
        int i = base + tid + j*256;
        if (i < M) s += deg[i];
    }
    sh[tid] = s;
    __syncthreads();
    for (int o = 128; o; o >>= 1){
        if (tid < o) sh[tid] += sh[tid + o];
        __syncthreads();
    }
    if (tid == 0) bsums[blockIdx.x] = sh[0];
}

__global__ void scanwrite_kernel(const int* __restrict__ deg, const int* __restrict__ bsums,
                                 int* __restrict__ rowptr, int* __restrict__ cur,
                                 float* __restrict__ dis, int M){
    __shared__ int sh[1024];
    __shared__ int base_s;
    int tid = threadIdx.x;
    int i = blockIdx.x*1024 + tid;
    if (tid == 0){
        int a = 0;
        for (int j = 0; j < blockIdx.x; j++) a += bsums[j];
        base_s = a;
    }
    int v = (i < M) ? deg[i] : 0;
    sh[tid] = v;
    __syncthreads();
    #pragma unroll
    for (int o = 1; o < 1024; o <<= 1){
        int t = (tid >= o) ? sh[tid - o] : 0;
        __syncthreads();
        sh[tid] += t;
        __syncthreads();
    }
    if (i < M){
        int excl = base_s + sh[tid] - v;
        rowptr[i] = excl;
        cur[i]    = excl;
        dis[i]    = rsqrtf(1.0f + (float)v);
        if (i == M-1) rowptr[M] = excl + v;
    }
}

// ---------------- CSR scatter (full graph only) ----------------
__global__ void scatter1_kernel(const int* __restrict__ src, const int* __restrict__ dst,
                                int* __restrict__ cur, int* __restrict__ csr){
    int e = blockIdx.x*blockDim.x + threadIdx.x;
    if (e >= DE) return;
    int pos = atomicAdd(&cur[dst[e]], 1);
    csr[pos] = src[e];
}

// ---------------- CSR2 built from CSR1 (no edge-list re-pass) ---------------
// warp per old node n: deg2[nidx[n]] = #kept sources in csr1 row of n
__global__ void csr2_count_kernel(const int* __restrict__ rp1, const int* __restrict__ csr1,
                                  const int* __restrict__ nidx, int* __restrict__ deg2){
    int n = (blockIdx.x*blockDim.x + threadIdx.x) >> 5;
    int lane = threadIdx.x & 31;
    if (n >= DN) return;
    int d = nidx[n];
    if (d < 0) return;
    int beg = rp1[n], end = rp1[n+1];
    int c = 0;
    for (int j = beg + lane; j < end; j += 32)
        if (nidx[csr1[j]] >= 0) c++;
    #pragma unroll
    for (int o = 16; o; o >>= 1) c += __shfl_xor_sync(0xffffffffu, c, o);
    if (lane == 0) deg2[d] = c;
}

// warp per old node n: fill csr2 row of nidx[n] with remapped kept sources
__global__ void csr2_fill_kernel(const int* __restrict__ rp1, const int* __restrict__ csr1,
                                 const int* __restrict__ nidx, const int* __restrict__ rp2,
                                 int* __restrict__ csr2){
    int n = (blockIdx.x*blockDim.x + threadIdx.x) >> 5;
    int lane = threadIdx.x & 31;
    if (n >= DN) return;
    int d = nidx[n];
    if (d < 0) return;
    int beg = rp1[n], end = rp1[n+1];
    int out = rp2[d];
    for (int j0 = beg; j0 < end; j0 += 32){
        int j = j0 + lane;
        int s = (j < end) ? nidx[csr1[j]] : -1;
        unsigned m = __ballot_sync(0xffffffffu, s >= 0);
        int off = __popc(m & ((1u << lane) - 1u));
        if (s >= 0) csr2[out + off] = s;
        out += __popc(m);
    }
}

// ---------------- 64-dim CSR gathers (warp per node, float2 lanes) ----------
__global__ void gather64_raw_kernel(const int* __restrict__ rowptr, const int* __restrict__ csr,
                                    const float* __restrict__ dis, const float* __restrict__ Hin,
                                    float* __restrict__ Hout, int M){
    int w = (blockIdx.x*blockDim.x + threadIdx.x) >> 5;
    int lane = threadIdx.x & 31;
    if (w >= M) return;
    int beg = rowptr[w], end = rowptr[w+1];
    float dn = dis[w];
    float2 h = ((const float2*)Hin)[(size_t)w*32 + lane];
    float s2 = dn*dn;
    float2 acc = make_float2(h.x*s2, h.y*s2);
    for (int j = beg; j < end; j++){
        int s = csr[j];
        float c = dis[s] * dn;
        float2 v = ((const float2*)Hin)[(size_t)s*32 + lane];
        acc.x += c*v.x; acc.y += c*v.y;
    }
    ((float2*)Hout)[(size_t)w*32 + lane] = acc;
}

__global__ void gather64_epi_kernel(const int* __restrict__ rowptr, const int* __restrict__ csr,
                                    const float* __restrict__ dis, const float* __restrict__ Hin,
                                    const float* __restrict__ bias, float* __restrict__ Hout, int M){
    int w = (blockIdx.x*blockDim.x + threadIdx.x) >> 5;
    int lane = threadIdx.x & 31;
    if (w >= M) return;
    int beg = rowptr[w], end = rowptr[w+1];
    float dn = dis[w];
    float2 h = ((const float2*)Hin)[(size_t)w*32 + lane];
    float s2 = dn*dn;
    float2 acc = make_float2(h.x*s2, h.y*s2);
    for (int j = beg; j < end; j++){
        int s = csr[j];
        float c = dis[s] * dn;
        float2 v = ((const float2*)Hin)[(size_t)s*32 + lane];
        acc.x += c*v.x; acc.y += c*v.y;
    }
    float2 b = ((const float2*)bias)[lane];
    acc.x = fmaxf(acc.x + b.x, 0.f);
    acc.y = fmaxf(acc.y + b.y, 0.f);
    ((float2*)Hout)[(size_t)w*32 + lane] = acc;
}

__global__ void gather64_reduce_kernel(const int* __restrict__ rowptr, const int* __restrict__ csr,
                                       const float* __restrict__ dis, const float* __restrict__ Hin,
                                       float* __restrict__ accOut){
    __shared__ float sh[64];
    const int lane = threadIdx.x & 31;
    const int wloc = threadIdx.x >> 5;
    const int wpb  = blockDim.x >> 5;
    if (threadIdx.x < 64) sh[threadIdx.x] = 0.f;
    __syncthreads();
    int w = blockIdx.x*wpb + wloc;
    int tw = gridDim.x*wpb;
    float2 sum = make_float2(0.f, 0.f);
    for (int n = w; n < DK; n += tw){
        int beg = rowptr[n], end = rowptr[n+1];
        float dn = dis[n];
        float2 h = ((const float2*)Hin)[(size_t)n*32 + lane];
        float s2 = dn*dn;
        float2 a = make_float2(h.x*s2, h.y*s2);
        for (int j = beg; j < end; j++){
            int s = csr[j];
            float c = dis[s] * dn;
            float2 v = ((const float2*)Hin)[(size_t)s*32 + lane];
            a.x += c*v.x; a.y += c*v.y;
        }
        sum.x += a.x; sum.y += a.y;
    }
    atomicAdd(&sh[2*lane],   sum.x);
    atomicAdd(&sh[2*lane+1], sum.y);
    __syncthreads();
    if (threadIdx.x < 64) atomicAdd(&accOut[threadIdx.x], sh[threadIdx.x]);
}

__global__ void write_out_kernel(const float* __restrict__ acc, const float* __restrict__ b4,
                                 float* __restrict__ out){
    if (threadIdx.x < 64)
        out[threadIdx.x] = acc[threadIdx.x] * (1.0f/(float)DK) + b4[threadIdx.x];
}

// ---------------- pooling: score (wnorm folded in) + radix select -----------
__global__ void score_kernel(const float* __restrict__ H, const float* __restrict__ w,
                             float* __restrict__ score, u64* __restrict__ key){
    __shared__ float swn;
    __shared__ float red[8];
    int tid = threadIdx.x;
    float q = (tid < 128) ? w[tid]*w[tid] : 0.f;
    #pragma unroll
    for (int o = 16; o; o >>= 1) q += __shfl_xor_sync(0xffffffffu, q, o);
    if ((tid & 31) == 0) red[tid >> 5] = q;
    __syncthreads();
    if (tid == 0) swn = sqrtf(red[0] + red[1] + red[2] + red[3]);
    __syncthreads();
    float wn = swn;

    int t = blockIdx.x*blockDim.x + tid;
    int n = t >> 5, lane = t & 31;
    if (n >= DN) return;
    float4 a = ((const float4*)H)[(size_t)n*32 + lane];
    float4 b = ((const float4*)w)[lane];
    float s = a.x*b.x + a.y*b.y + a.z*b.z + a.w*b.w;
    #pragma unroll
    for (int o = 16; o; o >>= 1) s += __shfl_xor_sync(0xffffffffu, s, o);
    if (lane == 0){
        s = tanhf(s / wn);
        score[n] = s;
        unsigned ub = __float_as_uint(s);
        ub = (ub & 0x80000000u) ? ~ub : (ub | 0x80000000u);   // order-preserving map
        key[n] = ((u64)ub << 32) | (u64)(0xffffffffu - (unsigned)n);  // distinct keys
    }
}

__global__ void hist_kernel(const u64* __restrict__ key, int* __restrict__ bins){
    __shared__ int sb[256];
    if (threadIdx.x < 256) sb[threadIdx.x] = 0;
    __syncthreads();
    for (int n = blockIdx.x*blockDim.x + threadIdx.x; n < DN; n += gridDim.x*blockDim.x)
        atomicAdd(&sb[(int)(key[n] >> 56)], 1);
    __syncthreads();
    if (threadIdx.x < 256 && sb[threadIdx.x]) atomicAdd(&bins[threadIdx.x], sb[threadIdx.x]);
}

__global__ void compact_kernel(const u64* __restrict__ key, const int* __restrict__ bins,
                               u64* __restrict__ cand, int* __restrict__ cnt){
    __shared__ int s_top;
    if (threadIdx.x == 0){
        int rem = DK;
        int bb = 0;
        for (int b = 255; b >= 0; b--){
            int c = bins[b];
            if (rem <= c){ bb = b; break; }
            rem -= c;
        }
        s_top = bb;
    }
    __syncthreads();
    u64 top = (u64)s_top;
    int n = blockIdx.x*blockDim.x + threadIdx.x;
    if (n >= DN) return;
    u64 k = key[n];
    if ((k >> 56) == top){
        int p = atomicAdd(cnt, 1);
        cand[p] = k;
    }
}

__global__ void finish_select_kernel(const u64* __restrict__ cand, const int* __restrict__ cntp,
                                     const int* __restrict__ gbins, u64* __restrict__ pfxp){
    __shared__ int bins[256];
    __shared__ u64 s_pfx;
    __shared__ int s_rem;
    const int tid = threadIdx.x;
    const int C = *cntp;
    if (tid == 0){
        int rem = DK;
        int bb = 0;
        for (int b = 255; b >= 0; b--){
            int c = gbins[b];
            if (rem <= c){ bb = b; break; }
            rem -= c;
        }
        s_pfx = ((u64)bb) << 56;
        s_rem = rem;
    }
    __syncthreads();
    for (int shift = 48; shift >= 0; shift -= 8){
        if (tid < 256) bins[tid] = 0;
        __syncthreads();
        u64 pfx = s_pfx;
        for (int i = tid; i < C; i += blockDim.x){
            u64 k = cand[i];
            if ((k >> (shift+8)) == (pfx >> (shift+8)))
                atomicAdd(&bins[(int)((k >> shift) & 0xFF)], 1);
        }
        __syncthreads();
        if (tid == 0){
            int rem = s_rem;
            for (int b = 255; b >= 0; b--){
                int c = bins[b];
                if (rem <= c){ s_pfx = pfx | (((u64)b) << shift); break; }
                rem -= c;
            }
            s_rem = rem;
        }
        __syncthreads();
    }
    if (tid == 0) *pfxp = s_pfx;
}

// ---------------- compaction: new_idx for kept nodes ----------------
__global__ void count_kept_kernel(const u64* __restrict__ key, const u64* __restrict__ pfxp,
                                  int* __restrict__ bsum){
    __shared__ int sh[256];
    u64 pfx = *pfxp;
    int tid = threadIdx.x;
    int base = blockIdx.x*1024 + tid*4;
    int c = 0;
    #pragma unroll
    for (int j = 0; j < 4; j++){
        int n = base + j;
        if (n < DN && key[n] >= pfx) c++;
    }
    sh[tid] = c;
    __syncthreads();
    for (int s = 128; s; s >>= 1){
        if (tid < s) sh[tid] += sh[tid + s];
        __syncthreads();
    }
    if (tid == 0) bsum[blockIdx.x] = sh[0];
}

__global__ void newidx_kernel(const u64* __restrict__ key, const u64* __restrict__ pfxp,
                              const int* __restrict__ bsum, int* __restrict__ newidx){
    __shared__ int sh[256];
    __shared__ int s_base;
    u64 pfx = *pfxp;
    int tid = threadIdx.x;
    if (tid == 0){
        int a = 0;
        for (int j = 0; j < blockIdx.x; j++) a += bsum[j];
        s_base = a;
    }
    int base = blockIdx.x*1024 + tid*4;
    int kept[4]; int cnt = 0;
    #pragma unroll
    for (int j = 0; j < 4; j++){
        int n = base + j;
        kept[j] = (n < DN && key[n] >= pfx) ? 1 : 0;
        cnt += kept[j];
    }
    sh[tid] = cnt;
    __syncthreads();
    for (int s = 1; s < 256; s <<= 1){
        int v = (tid >= s) ? sh[tid - s] : 0;
        __syncthreads();
        sh[tid] += v;
        __syncthreads();
    }
    int off = s_base + sh[tid] - cnt;   // exclusive prefix
    #pragma unroll
    for (int j = 0; j < 4; j++){
        int n = base + j;
        if (n < DN) newidx[n] = kept[j] ? off++ : -1;
    }
}

__global__ void build_hp_kernel(const float* __restrict__ H, const int* __restrict__ newidx,
                                const float* __restrict__ score, float* __restrict__ HP){
    int i = blockIdx.x*blockDim.x + threadIdx.x;
    if (i >= DN*32) return;
    int n = i >> 5;
    int ni = newidx[n];
    if (ni < 0) return;
    float s = score[n];
    float4 v = ((const float4*)H)[i];
    v.x *= s; v.y *= s; v.z *= s; v.w *= s;
    ((float4*)HP)[(size_t)ni*32 + (i & 31)] = v;
}

// ---------------- launch ----------------
extern "C" void kernel_launch(void* const* d_in, const int* in_sizes, int n_in,
                              void* d_out, int out_size){
    const float* x   = (const float*)d_in[0];
    const int*   ei  = (const int*)  d_in[1];
    const int*   src = ei;
    const int*   dst = ei + DE;
    const float* W1  = (const float*)d_in[3];
    const float* b1  = (const float*)d_in[4];
    const float* pw  = (const float*)d_in[5];
    const float* W2  = (const float*)d_in[6];
    const float* b2  = (const float*)d_in[7];
    const float* W3  = (const float*)d_in[8];
    const float* b3  = (const float*)d_in[9];
    const float* W4  = (const float*)d_in[10];
    const float* b4  = (const float*)d_in[11];
    float* out = (float*)d_out;

    void* basep = nullptr;
    cudaGetSymbolAddress(&basep, g_scratch);
    unsigned char* B = (unsigned char*)basep;
    float* xa    = (float*)(B + OFF_XA);
    float* ha    = (float*)(B + OFF_HA);
    float* hp    = (float*)(B + OFF_HP);
    float* gm    = (float*)(B + OFF_GM);
    float* t2    = (float*)(B + OFF_T2);
    float* dis1  = (float*)(B + OFF_DIS1);
    float* dis2  = (float*)(B + OFF_DIS2);
    int*   deg1  = (int*)  (B + OFF_DEG1);
    int*   deg2  = (int*)  (B + OFF_DEG2);
    int*   rp1   = (int*)  (B + OFF_RP1);
    int*   cur1  = (int*)  (B + OFF_CUR1);
    int*   rp2   = (int*)  (B + OFF_RP2);
    int*   cur2  = (int*)  (B + OFF_CUR2);
    int*   csr1  = (int*)  (B + OFF_CSR1);
    int*   csr2  = (int*)  (B + OFF_CSR2);
    float* score = (float*)(B + OFF_SCORE);
    u64*   key   = (u64*)  (B + OFF_KEY);
    u64*   cand  = (u64*)  (B + OFF_CAND);
    int*   nidx  = (int*)  (B + OFF_NEW);
    int*   bins  = (int*)  (B + OFF_BINS);
    int*   bsum  = (int*)  (B + OFF_BSUM);
    u64*   pfx   = (u64*)  (B + OFF_PFX);
    int*   ccnt  = (int*)  (B + OFF_CCNT);
    float* acc   = (float*)(B + OFF_ACC);

    const int T = 256;
    const int NB1 = (DN + 1023)/1024;   // 49
    const int NB2 = (DK + 1023)/1024;   // 40
    const int SMEM_G1 = (64*128 + 64*68)*4;    // 50176 B  (KIN=64, KOUT=128, ROWS=64)
    const int SMEM_G2 = (128*64 + 128*68)*4;   // 67584 B  (KIN=128, KOUT=64, ROWS=64)
    cudaFuncSetAttribute(gemm_tb<64,128,64,true>,  cudaFuncAttributeMaxDynamicSharedMemorySize, SMEM_G1);
    cudaFuncSetAttribute(gemm_tb<128,64,64,false>, cudaFuncAttributeMaxDynamicSharedMemorySize, SMEM_G2);

    // reset all per-replay state
    init_kernel<<<(DN+T-1)/T, T>>>(deg1, bins, acc, ccnt);

    // ---- CSR for the full graph ----
    deg_kernel<<<(DE+T-1)/T, T>>>(dst, deg1);
    blocksum_kernel<<<NB1, 256>>>(deg1, bsum, DN);
    scanwrite_kernel<<<NB1, 1024>>>(deg1, bsum, rp1, cur1, dis1, DN);
    scatter1_kernel<<<(DE+T-1)/T, T>>>(src, dst, cur1, csr1);

    // ---- conv1: gather in 64-dim input space, then GEMM(+bias+relu) ----
    gather64_raw_kernel<<<(DN*32+T-1)/T, T>>>(rp1, csr1, dis1, x, xa, DN);
    gemm_tb<64,128,64,true><<<(DN+63)/64, T, SMEM_G1>>>(xa, W1, b1, ha, DN);

    // ---- TopK pooling (exact radix select) ----
    score_kernel<<<(DN*32+T-1)/T, T>>>(ha, pw, score, key);
    hist_kernel<<<128, T>>>(key, bins);
    compact_kernel<<<(DN+T-1)/T, T>>>(key, bins, cand, ccnt);
    finish_select_kernel<<<1, 1024>>>(cand, ccnt, bins, pfx);
    count_kept_kernel<<<NBLK, T>>>(key, pfx, bsum);
    newidx_kernel<<<NBLK, T>>>(key, pfx, bsum, nidx);
    build_hp_kernel<<<(DN*32+T-1)/T, T>>>(ha, nidx, score, hp);

    // ---- pooled-graph CSR from CSR1 (no edge-list re-pass) ----
    csr2_count_kernel<<<(DN*32+T-1)/T, T>>>(rp1, csr1, nidx, deg2);
    blocksum_kernel<<<NB2, 256>>>(deg2, bsum, DK);
    scanwrite_kernel<<<NB2, 1024>>>(deg2, bsum, rp2, cur2, dis2, DK);
    csr2_fill_kernel<<<(DN*32+T-1)/T, T>>>(rp1, csr1, nidx, rp2, csr2);

    // ---- conv2 (128 -> 64): GEMM first, gather + bias + relu ----
    gemm_tb<128,64,64,false><<<(DK+63)/64, T, SMEM_G2>>>(hp, W2, nullptr, gm, DK);
    gather64_epi_kernel<<<(DK*32+T-1)/T, T>>>(rp2, csr2, dis2, gm, b2, t2, DK);

    // ---- conv3 (64 -> 128): gather in input space, then GEMM epi ----
    gather64_raw_kernel<<<(DK*32+T-1)/T, T>>>(rp2, csr2, dis2, t2, xa, DK);
    gemm_tb<64,128,64,true><<<(DK+63)/64, T, SMEM_G1>>>(xa, W3, b3, ha, DK);

    // ---- conv4 (128 -> 64): GEMM first, gather fused with global mean ----
    gemm_tb<128,64,64,false><<<(DK+63)/64, T, SMEM_G2>>>(ha, W4, nullptr, gm, DK);
    gather64_reduce_kernel<<<296, T>>>(rp2, csr2, dis2, gm, acc);
    write_out_kernel<<<1,64>>>(acc, b4, out);
}

// round 11
// speedup vs baseline: 1.0663x; 1.0663x over previous
#include <cuda_runtime.h>

typedef unsigned long long u64;

#define DN 50000
#define DE 800000
#define DK 40000

// ---------------- scratch layout (single __device__ blob) ----------------
static constexpr size_t OFF_XA   = 0;                               // DN*128 (gather-raw out, reused)
static constexpr size_t OFF_HA   = OFF_XA  + (size_t)DN*128*4;      // DN*128 conv out
static constexpr size_t OFF_GM   = OFF_HA  + (size_t)DN*128*4;      // DK*64 gemm out
static constexpr size_t OFF_T2   = OFF_GM  + (size_t)DK*64*4;       // DK*64 conv2 out
static constexpr size_t OFF_DIS1 = OFF_T2  + (size_t)DK*64*4;       // DN
static constexpr size_t OFF_DIS2 = OFF_DIS1 + (size_t)DN*4;         // DK
static constexpr size_t OFF_DEG1 = OFF_DIS2 + (size_t)DK*4;         // DN
static constexpr size_t OFF_DEG2 = OFF_DEG1 + (size_t)DN*4;         // DK
static constexpr size_t OFF_RP1  = OFF_DEG2 + (size_t)DK*4;         // DN+1
static constexpr size_t OFF_CUR1 = OFF_RP1  + (size_t)(DN+1)*4;     // DN
static constexpr size_t OFF_RP2  = OFF_CUR1 + (size_t)DN*4;         // DK+1
static constexpr size_t OFF_CUR2 = OFF_RP2  + (size_t)(DK+1)*4;     // DK
static constexpr size_t OFF_CSR1 = OFF_CUR2 + (size_t)DK*4;         // DE
static constexpr size_t OFF_CSR2 = OFF_CSR1 + (size_t)DE*4;         // DE
static constexpr size_t OFF_NS   = OFF_CSR2 + (size_t)DE*4;         // DE
static constexpr size_t OFF_ND   = OFF_NS   + (size_t)DE*4;         // DE
static constexpr size_t OFF_SCORE= OFF_ND   + (size_t)DE*4;         // DN
static constexpr size_t OFF_KEY  = OFF_SCORE+ (size_t)DN*4;         // DN u64
static constexpr size_t OFF_CAND = OFF_KEY  + (size_t)DN*8;         // DN u64
static constexpr size_t OFF_NEW  = OFF_CAND + (size_t)DN*8;         // DN
static constexpr size_t OFF_PERM = OFF_NEW  + (size_t)DN*4;         // DK
static constexpr size_t OFF_BINS = OFF_PERM + (size_t)DK*4;
static constexpr size_t OFF_BSUM = OFF_BINS + 256*4;                // 64
static constexpr size_t OFF_PFX  = OFF_BSUM + 64*4;
static constexpr size_t OFF_CCNT = OFF_PFX  + 8;
static constexpr size_t OFF_KCNT = OFF_CCNT + 4;
static constexpr size_t OFF_ACC  = OFF_KCNT + 4;
static constexpr size_t TOTAL_BYTES = OFF_ACC + 64*4;

__device__ __align__(256) unsigned char g_scratch[TOTAL_BYTES];

// ---------------- init: reset all per-replay state in one launch ------------
__global__ void init_kernel(int* deg1, int* deg2, int* bins, float* acc,
                            int* ccnt, int* kcnt){
    int i = blockIdx.x*blockDim.x + threadIdx.x;
    if (i < DN)  deg1[i] = 0;
    if (i < DK)  deg2[i] = 0;
    if (i < 256) bins[i] = 0;
    if (i < 64)  acc[i]  = 0.f;
    if (i == 0){ *ccnt = 0; *kcnt = 0; }
}

// ---------------- register-tiled GEMM (R5-proven) + optional bias/relu epi --
template<int KIN, int KOUT, int ROWS, bool EPI>
__global__ void gemm_rt(const float* __restrict__ X, const float* __restrict__ W,
                        const float* __restrict__ bias, float* __restrict__ Y, int M){
    extern __shared__ float sm[];
    float* sW = sm;                 // KIN*KOUT
    float* sX = sm + KIN*KOUT;      // ROWS*KIN
    const int tid = threadIdx.x;
    constexpr int CG = KOUT/4;
    constexpr int RG = ROWS/4;
    for (int i = tid; i < KIN*KOUT/4; i += blockDim.x)
        ((float4*)sW)[i] = ((const float4*)W)[i];
    const int row0 = blockIdx.x * ROWS;
    for (int i = tid; i < ROWS*KIN/4; i += blockDim.x){
        int r  = i / (KIN/4);
        int gr = row0 + r;
        ((float4*)sX)[i] = (gr < M) ? ((const float4*)X)[(size_t)gr*(KIN/4) + (i % (KIN/4))]
                                    : make_float4(0.f,0.f,0.f,0.f);
    }
    __syncthreads();
    const float4* w4 = (const float4*)sW;
    for (int it = tid; it < RG*CG; it += blockDim.x){
        int rg = it / CG, cg = it % CG;
        int r0 = rg*4;
        float4 a0 = make_float4(0,0,0,0), a1 = a0, a2 = a0, a3 = a0;
        #pragma unroll 8
        for (int k = 0; k < KIN; k++){
            float4 w = w4[k*CG + cg];
            float x0 = sX[(r0+0)*KIN + k];
            float x1 = sX[(r0+1)*KIN + k];
            float x2 = sX[(r0+2)*KIN + k];
            float x3 = sX[(r0+3)*KIN + k];
            a0.x += x0*w.x; a0.y += x0*w.y; a0.z += x0*w.z; a0.w += x0*w.w;
            a1.x += x1*w.x; a1.y += x1*w.y; a1.z += x1*w.z; a1.w += x1*w.w;
            a2.x += x2*w.x; a2.y += x2*w.y; a2.z += x2*w.z; a2.w += x2*w.w;
            a3.x += x3*w.x; a3.y += x3*w.y; a3.z += x3*w.z; a3.w += x3*w.w;
        }
        if (EPI){
            float4 b = ((const float4*)bias)[cg];
            a0.x = fmaxf(a0.x+b.x, 0.f); a0.y = fmaxf(a0.y+b.y, 0.f);
            a0.z = fmaxf(a0.z+b.z, 0.f); a0.w = fmaxf(a0.w+b.w, 0.f);
            a1.x = fmaxf(a1.x+b.x, 0.f); a1.y = fmaxf(a1.y+b.y, 0.f);
            a1.z = fmaxf(a1.z+b.z, 0.f); a1.w = fmaxf(a1.w+b.w, 0.f);
            a2.x = fmaxf(a2.x+b.x, 0.f); a2.y = fmaxf(a2.y+b.y, 0.f);
            a2.z = fmaxf(a2.z+b.z, 0.f); a2.w = fmaxf(a2.w+b.w, 0.f);
            a3.x = fmaxf(a3.x+b.x, 0.f); a3.y = fmaxf(a3.y+b.y, 0.f);
            a3.z = fmaxf(a3.z+b.z, 0.f); a3.w = fmaxf(a3.w+b.w, 0.f);
        }
        float4* yp = (float4*)Y;
        int gr = row0 + r0;
        if (gr+0 < M) yp[(size_t)(gr+0)*CG + cg] = a0;
        if (gr+1 < M) yp[(size_t)(gr+1)*CG + cg] = a1;
        if (gr+2 < M) yp[(size_t)(gr+2)*CG + cg] = a2;
        if (gr+3 < M) yp[(size_t)(gr+3)*CG + cg] = a3;
    }
}

// ---- GEMM with permuted + score-scaled input rows (conv2: hp never built) --
// Y = (ha[perm[r]] * score[perm[r]]) @ W
template<int KIN, int KOUT, int ROWS>
__global__ void gemm_perm(const float* __restrict__ X, const int* __restrict__ perm,
                          const float* __restrict__ score, const float* __restrict__ W,
                          float* __restrict__ Y, int M){
    extern __shared__ float sm[];
    float* sW = sm;
    float* sX = sm + KIN*KOUT;
    const int tid = threadIdx.x;
    constexpr int CG = KOUT/4;
    constexpr int RG = ROWS/4;
    for (int i = tid; i < KIN*KOUT/4; i += blockDim.x)
        ((float4*)sW)[i] = ((const float4*)W)[i];
    const int row0 = blockIdx.x * ROWS;
    for (int i = tid; i < ROWS*KIN/4; i += blockDim.x){
        int r  = i / (KIN/4);
        int gr = row0 + r;
        float4 v = make_float4(0.f,0.f,0.f,0.f);
        if (gr < M){
            int on = perm[gr];
            float sc = score[on];
            v = ((const float4*)X)[(size_t)on*(KIN/4) + (i % (KIN/4))];
            v.x *= sc; v.y *= sc; v.z *= sc; v.w *= sc;
        }
        ((float4*)sX)[i] = v;
    }
    __syncthreads();
    const float4* w4 = (const float4*)sW;
    for (int it = tid; it < RG*CG; it += blockDim.x){
        int rg = it / CG, cg = it % CG;
        int r0 = rg*4;
        float4 a0 = make_float4(0,0,0,0), a1 = a0, a2 = a0, a3 = a0;
        #pragma unroll 8
        for (int k = 0; k < KIN; k++){
            float4 w = w4[k*CG + cg];
            float x0 = sX[(r0+0)*KIN + k];
            float x1 = sX[(r0+1)*KIN + k];
            float x2 = sX[(r0+2)*KIN + k];
            float x3 = sX[(r0+3)*KIN + k];
            a0.x += x0*w.x; a0.y += x0*w.y; a0.z += x0*w.z; a0.w += x0*w.w;
            a1.x += x1*w.x; a1.y += x1*w.y; a1.z += x1*w.z; a1.w += x1*w.w;
            a2.x += x2*w.x; a2.y += x2*w.y; a2.z += x2*w.z; a2.w += x2*w.w;
            a3.x += x3*w.x; a3.y += x3*w.y; a3.z += x3*w.z; a3.w += x3*w.w;
        }
        float4* yp = (float4*)Y;
        int gr = row0 + r0;
        if (gr+0 < M) yp[(size_t)(gr+0)*CG + cg] = a0;
        if (gr+1 < M) yp[(size_t)(gr+1)*CG + cg] = a1;
        if (gr+2 < M) yp[(size_t)(gr+2)*CG + cg] = a2;
        if (gr+3 < M) yp[(size_t)(gr+3)*CG + cg] = a3;
    }
}

// ---------------- degree histogram ----------------
__global__ void deg_kernel(const int* __restrict__ dst, int* __restrict__ deg){
    int e = blockIdx.x*blockDim.x + threadIdx.x;
    if (e < DE) atomicAdd(&deg[dst[e]], 1);
}

// ---------------- 2-launch device-wide scan ----------------
__global__ void blocksum_kernel(const int* __restrict__ deg, int* __restrict__ bsums, int M){
    __shared__ int sh[256];
    int tid = threadIdx.x;
    int base = blockIdx.x * 1024;
    int s = 0;
    #pragma unroll
    for (int j = 0; j < 4; j++){
        int i = base + tid + j*256;
        if (i < M) s += deg[i];
    }
    sh[tid] = s;
    __syncthreads();
    for (int o = 128; o; o >>= 1){
        if (tid < o) sh[tid] += sh[tid + o];
        __syncthreads();
    }
    if (tid == 0) bsums[blockIdx.x] = sh[0];
}

__global__ void scanwrite_kernel(const int* __restrict__ deg, const int* __restrict__ bsums,
                                 int* __restrict__ rowptr, int* __restrict__ cur,
                                 float* __restrict__ dis, int M){
    __shared__ int sh[1024];
    __shared__ int base_s;
    int tid = threadIdx.x;
    int i = blockIdx.x*1024 + tid;
    if (tid == 0){
        int a = 0;
        for (int j = 0; j < blockIdx.x; j++) a += bsums[j];
        base_s = a;
    }
    int v = (i < M) ? deg[i] : 0;
    sh[tid] = v;
    __syncthreads();
    #pragma unroll
    for (int o = 1; o < 1024; o <<= 1){
        int t = (tid >= o) ? sh[tid - o] : 0;
        __syncthreads();
        sh[tid] += t;
        __syncthreads();
    }
    if (i < M){
        int excl = base_s + sh[tid] - v;
        rowptr[i] = excl;
        cur[i]    = excl;
        dis[i]    = rsqrtf(1.0f + (float)v);
        if (i == M-1) rowptr[M] = excl + v;
    }
}

// ---------------- CSR scatter ----------------
__global__ void scatter1_kernel(const int* __restrict__ src, const int* __restrict__ dst,
                                int* __restrict__ cur, int* __restrict__ csr){
    int e = blockIdx.x*blockDim.x + threadIdx.x;
    if (e >= DE) return;
    int pos = atomicAdd(&cur[dst[e]], 1);
    csr[pos] = src[e];
}

__global__ void scatter2_kernel(const int* __restrict__ ns, const int* __restrict__ nd,
                                int* __restrict__ cur, int* __restrict__ csr){
    int e = blockIdx.x*blockDim.x + threadIdx.x;
    if (e >= DE) return;
    int a = ns[e];
    if (a < 0) return;
    int pos = atomicAdd(&cur[nd[e]], 1);
    csr[pos] = a;
}

// ---------------- 64-dim CSR gathers (warp per node, float2 lanes) ----------
__global__ void gather64_raw_kernel(const int* __restrict__ rowptr, const int* __restrict__ csr,
                                    const float* __restrict__ dis, const float* __restrict__ Hin,
                                    float* __restrict__ Hout, int M){
    int w = (blockIdx.x*blockDim.x + threadIdx.x) >> 5;
    int lane = threadIdx.x & 31;
    if (w >= M) return;
    int beg = rowptr[w], end = rowptr[w+1];
    float dn = dis[w];
    float2 h = ((const float2*)Hin)[(size_t)w*32 + lane];
    float s2 = dn*dn;
    float2 acc = make_float2(h.x*s2, h.y*s2);
    for (int j = beg; j < end; j++){
        int s = csr[j];
        float c = dis[s] * dn;
        float2 v = ((const float2*)Hin)[(size_t)s*32 + lane];
        acc.x += c*v.x; acc.y += c*v.y;
    }
    ((float2*)Hout)[(size_t)w*32 + lane] = acc;
}

__global__ void gather64_epi_kernel(const int* __restrict__ rowptr, const int* __restrict__ csr,
                                    const float* __restrict__ dis, const float* __restrict__ Hin,
                                    const float* __restrict__ bias, float* __restrict__ Hout, int M){
    int w = (blockIdx.x*blockDim.x + threadIdx.x) >> 5;
    int lane = threadIdx.x & 31;
    if (w >= M) return;
    int beg = rowptr[w], end = rowptr[w+1];
    float dn = dis[w];
    float2 h = ((const float2*)Hin)[(size_t)w*32 + lane];
    float s2 = dn*dn;
    float2 acc = make_float2(h.x*s2, h.y*s2);
    for (int j = beg; j < end; j++){
        int s = csr[j];
        float c = dis[s] * dn;
        float2 v = ((const float2*)Hin)[(size_t)s*32 + lane];
        acc.x += c*v.x; acc.y += c*v.y;
    }
    float2 b = ((const float2*)bias)[lane];
    acc.x = fmaxf(acc.x + b.x, 0.f);
    acc.y = fmaxf(acc.y + b.y, 0.f);
    ((float2*)Hout)[(size_t)w*32 + lane] = acc;
}

__global__ void gather64_reduce_kernel(const int* __restrict__ rowptr, const int* __restrict__ csr,
                                       const float* __restrict__ dis, const float* __restrict__ Hin,
                                       float* __restrict__ accOut){
    __shared__ float sh[64];
    const int lane = threadIdx.x & 31;
    const int wloc = threadIdx.x >> 5;
    const int wpb  = blockDim.x >> 5;
    if (threadIdx.x < 64) sh[threadIdx.x] = 0.f;
    __syncthreads();
    int w = blockIdx.x*wpb + wloc;
    int tw = gridDim.x*wpb;
    float2 sum = make_float2(0.f, 0.f);
    for (int n = w; n < DK; n += tw){
        int beg = rowptr[n], end = rowptr[n+1];
        float dn = dis[n];
        float2 h = ((const float2*)Hin)[(size_t)n*32 + lane];
        float s2 = dn*dn;
        float2 a = make_float2(h.x*s2, h.y*s2);
        for (int j = beg; j < end; j++){
            int s = csr[j];
            float c = dis[s] * dn;
            float2 v = ((const float2*)Hin)[(size_t)s*32 + lane];
            a.x += c*v.x; a.y += c*v.y;
        }
        sum.x += a.x; sum.y += a.y;
    }
    atomicAdd(&sh[2*lane],   sum.x);
    atomicAdd(&sh[2*lane+1], sum.y);
    __syncthreads();
    if (threadIdx.x < 64) atomicAdd(&accOut[threadIdx.x], sh[threadIdx.x]);
}

__global__ void write_out_kernel(const float* __restrict__ acc, const float* __restrict__ b4,
                                 float* __restrict__ out){
    if (threadIdx.x < 64)
        out[threadIdx.x] = acc[threadIdx.x] * (1.0f/(float)DK) + b4[threadIdx.x];
}

// ---------------- pooling: score (wnorm folded in) + radix select -----------
__global__ void score_kernel(const float* __restrict__ H, const float* __restrict__ w,
                             float* __restrict__ score, u64* __restrict__ key){
    __shared__ float swn;
    __shared__ float red[8];
    int tid = threadIdx.x;
    float q = (tid < 128) ? w[tid]*w[tid] : 0.f;
    #pragma unroll
    for (int o = 16; o; o >>= 1) q += __shfl_xor_sync(0xffffffffu, q, o);
    if ((tid & 31) == 0) red[tid >> 5] = q;
    __syncthreads();
    if (tid == 0) swn = sqrtf(red[0] + red[1] + red[2] + red[3]);
    __syncthreads();
    float wn = swn;

    int t = blockIdx.x*blockDim.x + tid;
    int n = t >> 5, lane = t & 31;
    if (n >= DN) return;
    float4 a = ((const float4*)H)[(size_t)n*32 + lane];
    float4 b = ((const float4*)w)[lane];
    float s = a.x*b.x + a.y*b.y + a.z*b.z + a.w*b.w;
    #pragma unroll
    for (int o = 16; o; o >>= 1) s += __shfl_xor_sync(0xffffffffu, s, o);
    if (lane == 0){
        s = tanhf(s / wn);
        score[n] = s;
        unsigned ub = __float_as_uint(s);
        ub = (ub & 0x80000000u) ? ~ub : (ub | 0x80000000u);   // order-preserving map
        key[n] = ((u64)ub << 32) | (u64)(0xffffffffu - (unsigned)n);  // distinct keys
    }
}

__global__ void hist_kernel(const u64* __restrict__ key, int* __restrict__ bins){
    __shared__ int sb[256];
    if (threadIdx.x < 256) sb[threadIdx.x] = 0;
    __syncthreads();
    for (int n = blockIdx.x*blockDim.x + threadIdx.x; n < DN; n += gridDim.x*blockDim.x)
        atomicAdd(&sb[(int)(key[n] >> 56)], 1);
    __syncthreads();
    if (threadIdx.x < 256 && sb[threadIdx.x]) atomicAdd(&bins[threadIdx.x], sb[threadIdx.x]);
}

__global__ void compact_kernel(const u64* __restrict__ key, const int* __restrict__ bins,
                               u64* __restrict__ cand, int* __restrict__ cnt){
    __shared__ int s_top;
    if (threadIdx.x == 0){
        int rem = DK;
        int bb = 0;
        for (int b = 255; b >= 0; b--){
            int c = bins[b];
            if (rem <= c){ bb = b; break; }
            rem -= c;
        }
        s_top = bb;
    }
    __syncthreads();
    u64 top = (u64)s_top;
    int n = blockIdx.x*blockDim.x + threadIdx.x;
    if (n >= DN) return;
    u64 k = key[n];
    if ((k >> 56) == top){
        int p = atomicAdd(cnt, 1);
        cand[p] = k;
    }
}

__global__ void finish_select_kernel(const u64* __restrict__ cand, const int* __restrict__ cntp,
                                     const int* __restrict__ gbins, u64* __restrict__ pfxp){
    __shared__ int bins[256];
    __shared__ u64 s_pfx;
    __shared__ int s_rem;
    const int tid = threadIdx.x;
    const int C = *cntp;
    if (tid == 0){
        int rem = DK;
        int bb = 0;
        for (int b = 255; b >= 0; b--){
            int c = gbins[b];
            if (rem <= c){ bb = b; break; }
            rem -= c;
        }
        s_pfx = ((u64)bb) << 56;
        s_rem = rem;
    }
    __syncthreads();
    for (int shift = 48; shift >= 0; shift -= 8){
        if (tid < 256) bins[tid] = 0;
        __syncthreads();
        u64 pfx = s_pfx;
        for (int i = tid; i < C; i += blockDim.x){
            u64 k = cand[i];
            if ((k >> (shift+8)) == (pfx >> (shift+8)))
                atomicAdd(&bins[(int)((k >> shift) & 0xFF)], 1);
        }
        __syncthreads();
        if (tid == 0){
            int rem = s_rem;
            for (int b = 255; b >= 0; b--){
                int c = bins[b];
                if (rem <= c){ s_pfx = pfx | (((u64)b) << shift); break; }
                rem -= c;
            }
            s_rem = rem;
        }
        __syncthreads();
    }
    if (tid == 0) *pfxp = s_pfx;
}

// ---------------- kept-node labeling (order-free: output is label-invariant) -
__global__ void newidx_atomic_kernel(const u64* __restrict__ key, const u64* __restrict__ pfxp,
                                     int* __restrict__ cnt, int* __restrict__ nidx,
                                     int* __restrict__ perm){
    int n = blockIdx.x*blockDim.x + threadIdx.x;
    if (n >= DN) return;
    u64 pfx = *pfxp;
    if (key[n] >= pfx){
        int p = atomicAdd(cnt, 1);
        nidx[n] = p;
        perm[p] = n;
    } else {
        nidx[n] = -1;
    }
}

__global__ void remap_kernel(const int* __restrict__ src, const int* __restrict__ dst,
                             const int* __restrict__ newidx,
                             int* __restrict__ ns, int* __restrict__ nd, int* __restrict__ deg){
    int e = blockIdx.x*blockDim.x + threadIdx.x;
    if (e >= DE) return;
    int a = newidx[src[e]];
    int b = newidx[dst[e]];
    if (a >= 0 && b >= 0){
        ns[e] = a; nd[e] = b;
        atomicAdd(&deg[b], 1);
    } else { ns[e] = -1; nd[e] = -1; }
}

// ---------------- launch ----------------
extern "C" void kernel_launch(void* const* d_in, const int* in_sizes, int n_in,
                              void* d_out, int out_size){
    const float* x   = (const float*)d_in[0];
    const int*   ei  = (const int*)  d_in[1];
    const int*   src = ei;
    const int*   dst = ei + DE;
    const float* W1  = (const float*)d_in[3];
    const float* b1  = (const float*)d_in[4];
    const float* pw  = (const float*)d_in[5];
    const float* W2  = (const float*)d_in[6];
    const float* b2  = (const float*)d_in[7];
    const float* W3  = (const float*)d_in[8];
    const float* b3  = (const float*)d_in[9];
    const float* W4  = (const float*)d_in[10];
    const float* b4  = (const float*)d_in[11];
    float* out = (float*)d_out;

    void* basep = nullptr;
    cudaGetSymbolAddress(&basep, g_scratch);
    unsigned char* B = (unsigned char*)basep;
    float* xa    = (float*)(B + OFF_XA);
    float* ha    = (float*)(B + OFF_HA);
    float* gm    = (float*)(B + OFF_GM);
    float* t2    = (float*)(B + OFF_T2);
    float* dis1  = (float*)(B + OFF_DIS1);
    float* dis2  = (float*)(B + OFF_DIS2);
    int*   deg1  = (int*)  (B + OFF_DEG1);
    int*   deg2  = (int*)  (B + OFF_DEG2);
    int*   rp1   = (int*)  (B + OFF_RP1);
    int*   cur1  = (int*)  (B + OFF_CUR1);
    int*   rp2   = (int*)  (B + OFF_RP2);
    int*   cur2  = (int*)  (B + OFF_CUR2);
    int*   csr1  = (int*)  (B + OFF_CSR1);
    int*   csr2  = (int*)  (B + OFF_CSR2);
    int*   ns    = (int*)  (B + OFF_NS);
    int*   nd    = (int*)  (B + OFF_ND);
    float* score = (float*)(B + OFF_SCORE);
    u64*   key   = (u64*)  (B + OFF_KEY);
    u64*   cand  = (u64*)  (B + OFF_CAND);
    int*   nidx  = (int*)  (B + OFF_NEW);
    int*   perm  = (int*)  (B + OFF_PERM);
    int*   bins  = (int*)  (B + OFF_BINS);
    int*   bsum  = (int*)  (B + OFF_BSUM);
    u64*   pfx   = (u64*)  (B + OFF_PFX);
    int*   ccnt  = (int*)  (B + OFF_CCNT);
    int*   kcnt  = (int*)  (B + OFF_KCNT);
    float* acc   = (float*)(B + OFF_ACC);

    const int T = 256;
    const int NB1 = (DN + 1023)/1024;   // 49
    const int NB2 = (DK + 1023)/1024;   // 40
    const int SMEM_G1 = (64*128 + 64*64)*4;    // 48 KB (KIN=64, KOUT=128, ROWS=64)
    const int SMEM_G2 = (128*64 + 64*128)*4;   // 64 KB (KIN=128, KOUT=64, ROWS=64)
    cudaFuncSetAttribute(gemm_rt<128,64,64,false>, cudaFuncAttributeMaxDynamicSharedMemorySize, SMEM_G2);
    cudaFuncSetAttribute(gemm_perm<128,64,64>,     cudaFuncAttributeMaxDynamicSharedMemorySize, SMEM_G2);

    // reset all per-replay state
    init_kernel<<<(DN+T-1)/T, T>>>(deg1, deg2, bins, acc, ccnt, kcnt);

    // ---- CSR for the full graph ----
    deg_kernel<<<(DE+T-1)/T, T>>>(dst, deg1);
    blocksum_kernel<<<NB1, 256>>>(deg1, bsum, DN);
    scanwrite_kernel<<<NB1, 1024>>>(deg1, bsum, rp1, cur1, dis1, DN);
    scatter1_kernel<<<(DE+T-1)/T, T>>>(src, dst, cur1, csr1);

    // ---- conv1: gather in 64-dim input space, then GEMM(+bias+relu) ----
    gather64_raw_kernel<<<(DN*32+T-1)/T, T>>>(rp1, csr1, dis1, x, xa, DN);
    gemm_rt<64,128,64,true><<<(DN+63)/64, T, SMEM_G1>>>(xa, W1, b1, ha, DN);

    // ---- TopK pooling (exact radix select) ----
    score_kernel<<<(DN*32+T-1)/T, T>>>(ha, pw, score, key);
    hist_kernel<<<128, T>>>(key, bins);
    compact_kernel<<<(DN+T-1)/T, T>>>(key, bins, cand, ccnt);
    finish_select_kernel<<<1, 1024>>>(cand, ccnt, bins, pfx);
    newidx_atomic_kernel<<<(DN+T-1)/T, T>>>(key, pfx, kcnt, nidx, perm);

    // ---- pooled-graph CSR ----
    remap_kernel<<<(DE+T-1)/T, T>>>(src, dst, nidx, ns, nd, deg2);
    blocksum_kernel<<<NB2, 256>>>(deg2, bsum, DK);
    scanwrite_kernel<<<NB2, 1024>>>(deg2, bsum, rp2, cur2, dis2, DK);
    scatter2_kernel<<<(DE+T-1)/T, T>>>(ns, nd, cur2, csr2);

    // ---- conv2 (128 -> 64): perm-indirect GEMM (hp never materialized) ----
    gemm_perm<128,64,64><<<(DK+63)/64, T, SMEM_G2>>>(ha, perm, score, W2, gm, DK);
    gather64_epi_kernel<<<(DK*32+T-1)/T, T>>>(rp2, csr2, dis2, gm, b2, t2, DK);

    // ---- conv3 (64 -> 128): gather in input space, then GEMM epi ----
    gather64_raw_kernel<<<(DK*32+T-1)/T, T>>>(rp2, csr2, dis2, t2, xa, DK);
    gemm_rt<64,128,64,true><<<(DK+63)/64, T, SMEM_G1>>>(xa, W3, b3, ha, DK);

    // ---- conv4 (128 -> 64): GEMM, then gather fused with global mean ----
    gemm_rt<128,64,64,false><<<(DK+63)/64, T, SMEM_G2>>>(ha, W4, nullptr, gm, DK);
    gather64_reduce_kernel<<<296, T>>>(rp2, csr2, dis2, gm, acc);
    write_out_kernel<<<1,64>>>(acc, b4, out);
}

// round 12
// speedup vs baseline: 1.1119x; 1.0428x over previous
#include <cuda_runtime.h>

typedef unsigned long long u64;

#define DN 50000
#define DE 800000
#define DK 40000

// ---------------- scratch layout (single __device__ blob) ----------------
static constexpr size_t OFF_XA   = 0;                               // DN*128 (gather-raw out, reused)
static constexpr size_t OFF_HA   = OFF_XA  + (size_t)DN*128*4;      // DN*128 conv out
static constexpr size_t OFF_GM   = OFF_HA  + (size_t)DN*128*4;      // DK*64 gemm out
static constexpr size_t OFF_T2   = OFF_GM  + (size_t)DK*64*4;       // DK*64 conv2 out
static constexpr size_t OFF_DIS1 = OFF_T2  + (size_t)DK*64*4;       // DN
static constexpr size_t OFF_DIS2 = OFF_DIS1 + (size_t)DN*4;         // DK
static constexpr size_t OFF_DEG1 = OFF_DIS2 + (size_t)DK*4;         // DN
static constexpr size_t OFF_DEG2 = OFF_DEG1 + (size_t)DN*4;         // DK
static constexpr size_t OFF_RP1  = OFF_DEG2 + (size_t)DK*4;         // DN+1
static constexpr size_t OFF_CUR1 = OFF_RP1  + (size_t)(DN+1)*4;     // DN
static constexpr size_t OFF_RP2  = OFF_CUR1 + (size_t)DN*4;         // DK+1
static constexpr size_t OFF_CUR2 = OFF_RP2  + (size_t)(DK+1)*4;     // DK
static constexpr size_t OFF_CSR1 = OFF_CUR2 + (size_t)DK*4;         // DE
static constexpr size_t OFF_CSR2 = OFF_CSR1 + (size_t)DE*4;         // DE
static constexpr size_t OFF_NS   = OFF_CSR2 + (size_t)DE*4;         // DE
static constexpr size_t OFF_ND   = OFF_NS   + (size_t)DE*4;         // DE
static constexpr size_t OFF_SCORE= OFF_ND   + (size_t)DE*4;         // DN
static constexpr size_t OFF_KEY  = OFF_SCORE+ (size_t)DN*4;         // DN u64
static constexpr size_t OFF_CAND = OFF_KEY  + (size_t)DN*8;         // DN u64
static constexpr size_t OFF_NEW  = OFF_CAND + (size_t)DN*8;         // DN
static constexpr size_t OFF_PERM = OFF_NEW  + (size_t)DN*4;         // DK
static constexpr size_t OFF_BINS = OFF_PERM + (size_t)DK*4;
static constexpr size_t OFF_BSUM = OFF_BINS + 256*4;                // 64
static constexpr size_t OFF_PFX  = OFF_BSUM + 64*4;
static constexpr size_t OFF_CCNT = OFF_PFX  + 8;
static constexpr size_t OFF_KCNT = OFF_CCNT + 4;
static constexpr size_t OFF_ACC  = OFF_KCNT + 4;
static constexpr size_t TOTAL_BYTES = OFF_ACC + 64*4;

__device__ __align__(256) unsigned char g_scratch[TOTAL_BYTES];

// ---------------- init: reset all per-replay state in one launch ------------
__global__ void init_kernel(int* deg1, int* deg2, int* bins, float* acc,
                            int* ccnt, int* kcnt){
    int i = blockIdx.x*blockDim.x + threadIdx.x;
    if (i < DN)  deg1[i] = 0;
    if (i < DK)  deg2[i] = 0;
    if (i < 256) bins[i] = 0;
    if (i < 64)  acc[i]  = 0.f;
    if (i == 0){ *ccnt = 0; *kcnt = 0; }
}

// ---- GEMM compute core: k unrolled x4, float4 broadcast x-loads ------------
// (macro-free helper via inline function on shared pointers)
template<int KIN, int KOUT>
__device__ __forceinline__ void gemm_core(const float* sX, const float* sW,
                                          int r0, int cg,
                                          float4& a0, float4& a1, float4& a2, float4& a3){
    constexpr int CG = KOUT/4;
    const float4* w4 = (const float4*)sW;
    #pragma unroll 4
    for (int k = 0; k < KIN; k += 4){
        float4 xv0 = *(const float4*)&sX[(r0+0)*KIN + k];
        float4 xv1 = *(const float4*)&sX[(r0+1)*KIN + k];
        float4 xv2 = *(const float4*)&sX[(r0+2)*KIN + k];
        float4 xv3 = *(const float4*)&sX[(r0+3)*KIN + k];
        float4 w;
        w = w4[(k+0)*CG + cg];
        a0.x += xv0.x*w.x; a0.y += xv0.x*w.y; a0.z += xv0.x*w.z; a0.w += xv0.x*w.w;
        a1.x += xv1.x*w.x; a1.y += xv1.x*w.y; a1.z += xv1.x*w.z; a1.w += xv1.x*w.w;
        a2.x += xv2.x*w.x; a2.y += xv2.x*w.y; a2.z += xv2.x*w.z; a2.w += xv2.x*w.w;
        a3.x += xv3.x*w.x; a3.y += xv3.x*w.y; a3.z += xv3.x*w.z; a3.w += xv3.x*w.w;
        w = w4[(k+1)*CG + cg];
        a0.x += xv0.y*w.x; a0.y += xv0.y*w.y; a0.z += xv0.y*w.z; a0.w += xv0.y*w.w;
        a1.x += xv1.y*w.x; a1.y += xv1.y*w.y; a1.z += xv1.y*w.z; a1.w += xv1.y*w.w;
        a2.x += xv2.y*w.x; a2.y += xv2.y*w.y; a2.z += xv2.y*w.z; a2.w += xv2.y*w.w;
        a3.x += xv3.y*w.x; a3.y += xv3.y*w.y; a3.z += xv3.y*w.z; a3.w += xv3.y*w.w;
        w = w4[(k+2)*CG + cg];
        a0.x += xv0.z*w.x; a0.y += xv0.z*w.y; a0.z += xv0.z*w.z; a0.w += xv0.z*w.w;
        a1.x += xv1.z*w.x; a1.y += xv1.z*w.y; a1.z += xv1.z*w.z; a1.w += xv1.z*w.w;
        a2.x += xv2.z*w.x; a2.y += xv2.z*w.y; a2.z += xv2.z*w.z; a2.w += xv2.z*w.w;
        a3.x += xv3.z*w.x; a3.y += xv3.z*w.y; a3.z += xv3.z*w.z; a3.w += xv3.z*w.w;
        w = w4[(k+3)*CG + cg];
        a0.x += xv0.w*w.x; a0.y += xv0.w*w.y; a0.z += xv0.w*w.z; a0.w += xv0.w*w.w;
        a1.x += xv1.w*w.x; a1.y += xv1.w*w.y; a1.z += xv1.w*w.z; a1.w += xv1.w*w.w;
        a2.x += xv2.w*w.x; a2.y += xv2.w*w.y; a2.z += xv2.w*w.z; a2.w += xv2.w*w.w;
        a3.x += xv3.w*w.x; a3.y += xv3.w*w.y; a3.z += xv3.w*w.z; a3.w += xv3.w*w.w;
    }
}

// ---------------- register-tiled GEMM + optional bias/relu epilogue ---------
template<int KIN, int KOUT, int ROWS, bool EPI>
__global__ void gemm_rt(const float* __restrict__ X, const float* __restrict__ W,
                        const float* __restrict__ bias, float* __restrict__ Y, int M){
    extern __shared__ float sm[];
    float* sW = sm;                 // KIN*KOUT
    float* sX = sm + KIN*KOUT;      // ROWS*KIN
    const int tid = threadIdx.x;
    constexpr int CG = KOUT/4;
    constexpr int RG = ROWS/4;
    for (int i = tid; i < KIN*KOUT/4; i += blockDim.x)
        ((float4*)sW)[i] = ((const float4*)W)[i];
    const int row0 = blockIdx.x * ROWS;
    for (int i = tid; i < ROWS*KIN/4; i += blockDim.x){
        int r  = i / (KIN/4);
        int gr = row0 + r;
        ((float4*)sX)[i] = (gr < M) ? ((const float4*)X)[(size_t)gr*(KIN/4) + (i % (KIN/4))]
                                    : make_float4(0.f,0.f,0.f,0.f);
    }
    __syncthreads();
    for (int it = tid; it < RG*CG; it += blockDim.x){
        int rg = it / CG, cg = it % CG;
        int r0 = rg*4;
        float4 a0 = make_float4(0,0,0,0), a1 = a0, a2 = a0, a3 = a0;
        gemm_core<KIN,KOUT>(sX, sW, r0, cg, a0, a1, a2, a3);
        if (EPI){
            float4 b = ((const float4*)bias)[cg];
            a0.x = fmaxf(a0.x+b.x, 0.f); a0.y = fmaxf(a0.y+b.y, 0.f);
            a0.z = fmaxf(a0.z+b.z, 0.f); a0.w = fmaxf(a0.w+b.w, 0.f);
            a1.x = fmaxf(a1.x+b.x, 0.f); a1.y = fmaxf(a1.y+b.y, 0.f);
            a1.z = fmaxf(a1.z+b.z, 0.f); a1.w = fmaxf(a1.w+b.w, 0.f);
            a2.x = fmaxf(a2.x+b.x, 0.f); a2.y = fmaxf(a2.y+b.y, 0.f);
            a2.z = fmaxf(a2.z+b.z, 0.f); a2.w = fmaxf(a2.w+b.w, 0.f);
            a3.x = fmaxf(a3.x+b.x, 0.f); a3.y = fmaxf(a3.y+b.y, 0.f);
            a3.z = fmaxf(a3.z+b.z, 0.f); a3.w = fmaxf(a3.w+b.w, 0.f);
        }
        float4* yp = (float4*)Y;
        int gr = row0 + r0;
        if (gr+0 < M) yp[(size_t)(gr+0)*CG + cg] = a0;
        if (gr+1 < M) yp[(size_t)(gr+1)*CG + cg] = a1;
        if (gr+2 < M) yp[(size_t)(gr+2)*CG + cg] = a2;
        if (gr+3 < M) yp[(size_t)(gr+3)*CG + cg] = a3;
    }
}

// ---- GEMM with permuted + score-scaled input rows (conv2) ------------------
template<int KIN, int KOUT, int ROWS>
__global__ void gemm_perm(const float* __restrict__ X, const int* __restrict__ perm,
                          const float* __restrict__ score, const float* __restrict__ W,
                          float* __restrict__ Y, int M){
    extern __shared__ float sm[];
    float* sW = sm;
    float* sX = sm + KIN*KOUT;
    const int tid = threadIdx.x;
    constexpr int CG = KOUT/4;
    constexpr int RG = ROWS/4;
    for (int i = tid; i < KIN*KOUT/4; i += blockDim.x)
        ((float4*)sW)[i] = ((const float4*)W)[i];
    const int row0 = blockIdx.x * ROWS;
    for (int i = tid; i < ROWS*KIN/4; i += blockDim.x){
        int r  = i / (KIN/4);
        int gr = row0 + r;
        float4 v = make_float4(0.f,0.f,0.f,0.f);
        if (gr < M){
            int on = perm[gr];
            float sc = score[on];
            v = ((const float4*)X)[(size_t)on*(KIN/4) + (i % (KIN/4))];
            v.x *= sc; v.y *= sc; v.z *= sc; v.w *= sc;
        }
        ((float4*)sX)[i] = v;
    }
    __syncthreads();
    for (int it = tid; it < RG*CG; it += blockDim.x){
        int rg = it / CG, cg = it % CG;
        int r0 = rg*4;
        float4 a0 = make_float4(0,0,0,0), a1 = a0, a2 = a0, a3 = a0;
        gemm_core<KIN,KOUT>(sX, sW, r0, cg, a0, a1, a2, a3);
        float4* yp = (float4*)Y;
        int gr = row0 + r0;
        if (gr+0 < M) yp[(size_t)(gr+0)*CG + cg] = a0;
        if (gr+1 < M) yp[(size_t)(gr+1)*CG + cg] = a1;
        if (gr+2 < M) yp[(size_t)(gr+2)*CG + cg] = a2;
        if (gr+3 < M) yp[(size_t)(gr+3)*CG + cg] = a3;
    }
}

// ---------------- degree histogram ----------------
__global__ void deg_kernel(const int* __restrict__ dst, int* __restrict__ deg){
    int e = blockIdx.x*blockDim.x + threadIdx.x;
    if (e < DE) atomicAdd(&deg[dst[e]], 1);
}

// ---------------- 2-launch device-wide scan ----------------
__global__ void blocksum_kernel(const int* __restrict__ deg, int* __restrict__ bsums, int M){
    __shared__ int sh[256];
    int tid = threadIdx.x;
    int base = blockIdx.x * 1024;
    int s = 0;
    #pragma unroll
    for (int j = 0; j < 4; j++){
        int i = base + tid + j*256;
        if (i < M) s += deg[i];
    }
    sh[tid] = s;
    __syncthreads();
    for (int o = 128; o; o >>= 1){
        if (tid < o) sh[tid] += sh[tid + o];
        __syncthreads();
    }
    if (tid == 0) bsums[blockIdx.x] = sh[0];
}

// warp-shuffle scan: 2 syncthreads total
__global__ void scanwrite_kernel(const int* __restrict__ deg, const int* __restrict__ bsums,
                                 int* __restrict__ rowptr, int* __restrict__ cur,
                                 float* __restrict__ dis, int M){
    __shared__ int wsum[32];
    __shared__ int base_s;
    const int tid = threadIdx.x;
    const int lane = tid & 31;
    const int wid  = tid >> 5;
    const int i = blockIdx.x*1024 + tid;
    int v = (i < M) ? deg[i] : 0;
    if (tid == 0){
        int a = 0;
        for (int j = 0; j < blockIdx.x; j++) a += bsums[j];
        base_s = a;
    }
    // warp-inclusive scan
    int s = v;
    #pragma unroll
    for (int o = 1; o < 32; o <<= 1){
        int t = __shfl_up_sync(0xffffffffu, s, o);
        if (lane >= o) s += t;
    }
    if (lane == 31) wsum[wid] = s;
    __syncthreads();
    if (wid == 0){
        int t = wsum[lane];
        #pragma unroll
        for (int o = 1; o < 32; o <<= 1){
            int u = __shfl_up_sync(0xffffffffu, t, o);
            if (lane >= o) t += u;
        }
        wsum[lane] = t;
    }
    __syncthreads();
    int woff = wid ? wsum[wid-1] : 0;
    if (i < M){
        int excl = base_s + woff + s - v;
        rowptr[i] = excl;
        cur[i]    = excl;
        dis[i]    = rsqrtf(1.0f + (float)v);
        if (i == M-1) rowptr[M] = excl + v;
    }
}

// ---------------- CSR scatter ----------------
__global__ void scatter1_kernel(const int* __restrict__ src, const int* __restrict__ dst,
                                int* __restrict__ cur, int* __restrict__ csr){
    int e = blockIdx.x*blockDim.x + threadIdx.x;
    if (e >= DE) return;
    int pos = atomicAdd(&cur[dst[e]], 1);
    csr[pos] = src[e];
}

__global__ void scatter2_kernel(const int* __restrict__ ns, const int* __restrict__ nd,
                                int* __restrict__ cur, int* __restrict__ csr){
    int e = blockIdx.x*blockDim.x + threadIdx.x;
    if (e >= DE) return;
    int a = ns[e];
    if (a < 0) return;
    int pos = atomicAdd(&cur[nd[e]], 1);
    csr[pos] = a;
}

// ---------------- 64-dim CSR gathers (warp per node, float2 lanes) ----------
__global__ void gather64_raw_kernel(const int* __restrict__ rowptr, const int* __restrict__ csr,
                                    const float* __restrict__ dis, const float* __restrict__ Hin,
                                    float* __restrict__ Hout, int M){
    int w = (blockIdx.x*blockDim.x + threadIdx.x) >> 5;
    int lane = threadIdx.x & 31;
    if (w >= M) return;
    int beg = rowptr[w], end = rowptr[w+1];
    float dn = dis[w];
    float2 h = ((const float2*)Hin)[(size_t)w*32 + lane];
    float s2 = dn*dn;
    float2 acc = make_float2(h.x*s2, h.y*s2);
    for (int j = beg; j < end; j++){
        int s = csr[j];
        float c = dis[s] * dn;
        float2 v = ((const float2*)Hin)[(size_t)s*32 + lane];
        acc.x += c*v.x; acc.y += c*v.y;
    }
    ((float2*)Hout)[(size_t)w*32 + lane] = acc;
}

__global__ void gather64_epi_kernel(const int* __restrict__ rowptr, const int* __restrict__ csr,
                                    const float* __restrict__ dis, const float* __restrict__ Hin,
                                    const float* __restrict__ bias, float* __restrict__ Hout, int M){
    int w = (blockIdx.x*blockDim.x + threadIdx.x) >> 5;
    int lane = threadIdx.x & 31;
    if (w >= M) return;
    int beg = rowptr[w], end = rowptr[w+1];
    float dn = dis[w];
    float2 h = ((const float2*)Hin)[(size_t)w*32 + lane];
    float s2 = dn*dn;
    float2 acc = make_float2(h.x*s2, h.y*s2);
    for (int j = beg; j < end; j++){
        int s = csr[j];
        float c = dis[s] * dn;
        float2 v = ((const float2*)Hin)[(size_t)s*32 + lane];
        acc.x += c*v.x; acc.y += c*v.y;
    }
    float2 b = ((const float2*)bias)[lane];
    acc.x = fmaxf(acc.x + b.x, 0.f);
    acc.y = fmaxf(acc.y + b.y, 0.f);
    ((float2*)Hout)[(size_t)w*32 + lane] = acc;
}

__global__ void gather64_reduce_kernel(const int* __restrict__ rowptr, const int* __restrict__ csr,
                                       const float* __restrict__ dis, const float* __restrict__ Hin,
                                       float* __restrict__ accOut){
    __shared__ float sh[64];
    const int lane = threadIdx.x & 31;
    const int wloc = threadIdx.x >> 5;
    const int wpb  = blockDim.x >> 5;
    if (threadIdx.x < 64) sh[threadIdx.x] = 0.f;
    __syncthreads();
    int w = blockIdx.x*wpb + wloc;
    int tw = gridDim.x*wpb;
    float2 sum = make_float2(0.f, 0.f);
    for (int n = w; n < DK; n += tw){
        int beg = rowptr[n], end = rowptr[n+1];
        float dn = dis[n];
        float2 h = ((const float2*)Hin)[(size_t)n*32 + lane];
        float s2 = dn*dn;
        float2 a = make_float2(h.x*s2, h.y*s2);
        for (int j = beg; j < end; j++){
            int s = csr[j];
            float c = dis[s] * dn;
            float2 v = ((const float2*)Hin)[(size_t)s*32 + lane];
            a.x += c*v.x; a.y += c*v.y;
        }
        sum.x += a.x; sum.y += a.y;
    }
    atomicAdd(&sh[2*lane],   sum.x);
    atomicAdd(&sh[2*lane+1], sum.y);
    __syncthreads();
    if (threadIdx.x < 64) atomicAdd(&accOut[threadIdx.x], sh[threadIdx.x]);
}

__global__ void write_out_kernel(const float* __restrict__ acc, const float* __restrict__ b4,
                                 float* __restrict__ out){
    if (threadIdx.x < 64)
        out[threadIdx.x] = acc[threadIdx.x] * (1.0f/(float)DK) + b4[threadIdx.x];
}

// ---------------- pooling: score (wnorm folded in) + radix select -----------
__global__ void score_kernel(const float* __restrict__ H, const float* __restrict__ w,
                             float* __restrict__ score, u64* __restrict__ key){
    __shared__ float swn;
    __shared__ float red[8];
    int tid = threadIdx.x;
    float q = (tid < 128) ? w[tid]*w[tid] : 0.f;
    #pragma unroll
    for (int o = 16; o; o >>= 1) q += __shfl_xor_sync(0xffffffffu, q, o);
    if ((tid & 31) == 0) red[tid >> 5] = q;
    __syncthreads();
    if (tid == 0) swn = sqrtf(red[0] + red[1] + red[2] + red[3]);
    __syncthreads();
    float wn = swn;

    int t = blockIdx.x*blockDim.x + tid;
    int n = t >> 5, lane = t & 31;
    if (n >= DN) return;
    float4 a = ((const float4*)H)[(size_t)n*32 + lane];
    float4 b = ((const float4*)w)[lane];
    float s = a.x*b.x + a.y*b.y + a.z*b.z + a.w*b.w;
    #pragma unroll
    for (int o = 16; o; o >>= 1) s += __shfl_xor_sync(0xffffffffu, s, o);
    if (lane == 0){
        s = tanhf(s / wn);
        score[n] = s;
        unsigned ub = __float_as_uint(s);
        ub = (ub & 0x80000000u) ? ~ub : (ub | 0x80000000u);   // order-preserving map
        key[n] = ((u64)ub << 32) | (u64)(0xffffffffu - (unsigned)n);  // distinct keys
    }
}

__global__ void hist_kernel(const u64* __restrict__ key, int* __restrict__ bins){
    __shared__ int sb[256];
    if (threadIdx.x < 256) sb[threadIdx.x] = 0;
    __syncthreads();
    for (int n = blockIdx.x*blockDim.x + threadIdx.x; n < DN; n += gridDim.x*blockDim.x)
        atomicAdd(&sb[(int)(key[n] >> 56)], 1);
    __syncthreads();
    if (threadIdx.x < 256 && sb[threadIdx.x]) atomicAdd(&bins[threadIdx.x], sb[threadIdx.x]);
}

__global__ void compact_kernel(const u64* __restrict__ key, const int* __restrict__ bins,
                               u64* __restrict__ cand, int* __restrict__ cnt){
    __shared__ int s_top;
    if (threadIdx.x == 0){
        int rem = DK;
        int bb = 0;
        for (int b = 255; b >= 0; b--){
            int c = bins[b];
            if (rem <= c){ bb = b; break; }
            rem -= c;
        }
        s_top = bb;
    }
    __syncthreads();
    u64 top = (u64)s_top;
    int n = blockIdx.x*blockDim.x + threadIdx.x;
    if (n >= DN) return;
    u64 k = key[n];
    if ((k >> 56) == top){
        int p = atomicAdd(cnt, 1);
        cand[p] = k;
    }
}

__global__ void finish_select_kernel(const u64* __restrict__ cand, const int* __restrict__ cntp,
                                     const int* __restrict__ gbins, u64* __restrict__ pfxp){
    __shared__ int bins[256];
    __shared__ u64 s_pfx;
    __shared__ int s_rem;
    const int tid = threadIdx.x;
    const int C = *cntp;
    if (tid == 0){
        int rem = DK;
        int bb = 0;
        for (int b = 255; b >= 0; b--){
            int c = gbins[b];
            if (rem <= c){ bb = b; break; }
            rem -= c;
        }
        s_pfx = ((u64)bb) << 56;
        s_rem = rem;
    }
    __syncthreads();
    for (int shift = 48; shift >= 0; shift -= 8){
        if (tid < 256) bins[tid] = 0;
        __syncthreads();
        u64 pfx = s_pfx;
        for (int i = tid; i < C; i += blockDim.x){
            u64 k = cand[i];
            if ((k >> (shift+8)) == (pfx >> (shift+8)))
                atomicAdd(&bins[(int)((k >> shift) & 0xFF)], 1);
        }
        __syncthreads();
        if (tid == 0){
            int rem = s_rem;
            for (int b = 255; b >= 0; b--){
                int c = bins[b];
                if (rem <= c){ s_pfx = pfx | (((u64)b) << shift); break; }
                rem -= c;
            }
            s_rem = rem;
        }
        __syncthreads();
    }
    if (tid == 0) *pfxp = s_pfx;
}

// ---------------- kept-node labeling (order-free: output is label-invariant) -
__global__ void newidx_atomic_kernel(const u64* __restrict__ key, const u64* __restrict__ pfxp,
                                     int* __restrict__ cnt, int* __restrict__ nidx,
                                     int* __restrict__ perm){
    int n = blockIdx.x*blockDim.x + threadIdx.x;
    if (n >= DN) return;
    u64 pfx = *pfxp;
    if (key[n] >= pfx){
        int p = atomicAdd(cnt, 1);
        nidx[n] = p;
        perm[p] = n;
    } else {
        nidx[n] = -1;
    }
}

__global__ void remap_kernel(const int* __restrict__ src, const int* __restrict__ dst,
                             const int* __restrict__ newidx,
                             int* __restrict__ ns, int* __restrict__ nd, int* __restrict__ deg){
    int e = blockIdx.x*blockDim.x + threadIdx.x;
    if (e >= DE) return;
    int a = newidx[src[e]];
    int b = newidx[dst[e]];
    if (a >= 0 && b >= 0){
        ns[e] = a; nd[e] = b;
        atomicAdd(&deg[b], 1);
    } else { ns[e] = -1; nd[e] = -1; }
}

// ---------------- launch ----------------
extern "C" void kernel_launch(void* const* d_in, const int* in_sizes, int n_in,
                              void* d_out, int out_size){
    const float* x   = (const float*)d_in[0];
    const int*   ei  = (const int*)  d_in[1];
    const int*   src = ei;
    const int*   dst = ei + DE;
    const float* W1  = (const float*)d_in[3];
    const float* b1  = (const float*)d_in[4];
    const float* pw  = (const float*)d_in[5];
    const float* W2  = (const float*)d_in[6];
    const float* b2  = (const float*)d_in[7];
    const float* W3  = (const float*)d_in[8];
    const float* b3  = (const float*)d_in[9];
    const float* W4  = (const float*)d_in[10];
    const float* b4  = (const float*)d_in[11];
    float* out = (float*)d_out;

    void* basep = nullptr;
    cudaGetSymbolAddress(&basep, g_scratch);
    unsigned char* B = (unsigned char*)basep;
    float* xa    = (float*)(B + OFF_XA);
    float* ha    = (float*)(B + OFF_HA);
    float* gm    = (float*)(B + OFF_GM);
    float* t2    = (float*)(B + OFF_T2);
    float* dis1  = (float*)(B + OFF_DIS1);
    float* dis2  = (float*)(B + OFF_DIS2);
    int*   deg1  = (int*)  (B + OFF_DEG1);
    int*   deg2  = (int*)  (B + OFF_DEG2);
    int*   rp1   = (int*)  (B + OFF_RP1);
    int*   cur1  = (int*)  (B + OFF_CUR1);
    int*   rp2   = (int*)  (B + OFF_RP2);
    int*   cur2  = (int*)  (B + OFF_CUR2);
    int*   csr1  = (int*)  (B + OFF_CSR1);
    int*   csr2  = (int*)  (B + OFF_CSR2);
    int*   ns    = (int*)  (B + OFF_NS);
    int*   nd    = (int*)  (B + OFF_ND);
    float* score = (float*)(B + OFF_SCORE);
    u64*   key   = (u64*)  (B + OFF_KEY);
    u64*   cand  = (u64*)  (B + OFF_CAND);
    int*   nidx  = (int*)  (B + OFF_NEW);
    int*   perm  = (int*)  (B + OFF_PERM);
    int*   bins  = (int*)  (B + OFF_BINS);
    int*   bsum  = (int*)  (B + OFF_BSUM);
    u64*   pfx   = (u64*)  (B + OFF_PFX);
    int*   ccnt  = (int*)  (B + OFF_CCNT);
    int*   kcnt  = (int*)  (B + OFF_KCNT);
    float* acc   = (float*)(B + OFF_ACC);

    const int T = 256;
    const int NB1 = (DN + 1023)/1024;   // 49
    const int NB2 = (DK + 1023)/1024;   // 40
    const int SMEM_G1 = (64*128 + 64*64)*4;    // 48 KB (KIN=64, KOUT=128, ROWS=64)
    const int SMEM_G2 = (128*64 + 64*128)*4;   // 64 KB (KIN=128, KOUT=64, ROWS=64)
    cudaFuncSetAttribute(gemm_rt<128,64,64,false>, cudaFuncAttributeMaxDynamicSharedMemorySize, SMEM_G2);
    cudaFuncSetAttribute(gemm_perm<128,64,64>,     cudaFuncAttributeMaxDynamicSharedMemorySize, SMEM_G2);

    // reset all per-replay state
    init_kernel<<<(DN+T-1)/T, T>>>(deg1, deg2, bins, acc, ccnt, kcnt);

    // ---- CSR for the full graph ----
    deg_kernel<<<(DE+T-1)/T, T>>>(dst, deg1);
    blocksum_kernel<<<NB1, 256>>>(deg1, bsum, DN);
    scanwrite_kernel<<<NB1, 1024>>>(deg1, bsum, rp1, cur1, dis1, DN);
    scatter1_kernel<<<(DE+T-1)/T, T>>>(src, dst, cur1, csr1);

    // ---- conv1: gather in 64-dim input space, then GEMM(+bias+relu) ----
    gather64_raw_kernel<<<(DN*32+T-1)/T, T>>>(rp1, csr1, dis1, x, xa, DN);
    gemm_rt<64,128,64,true><<<(DN+63)/64, T, SMEM_G1>>>(xa, W1, b1, ha, DN);

    // ---- TopK pooling (exact radix select) ----
    score_kernel<<<(DN*32+T-1)/T, T>>>(ha, pw, score, key);
    hist_kernel<<<128, T>>>(key, bins);
    compact_kernel<<<(DN+T-1)/T, T>>>(key, bins, cand, ccnt);
    finish_select_kernel<<<1, 1024>>>(cand, ccnt, bins, pfx);
    newidx_atomic_kernel<<<(DN+T-1)/T, T>>>(key, pfx, kcnt, nidx, perm);

    // ---- pooled-graph CSR ----
    remap_kernel<<<(DE+T-1)/T, T>>>(src, dst, nidx, ns, nd, deg2);
    blocksum_kernel<<<NB2, 256>>>(deg2, bsum, DK);
    scanwrite_kernel<<<NB2, 1024>>>(deg2, bsum, rp2, cur2, dis2, DK);
    scatter2_kernel<<<(DE+T-1)/T, T>>>(ns, nd, cur2, csr2);

    // ---- conv2 (128 -> 64): perm-indirect GEMM (hp never materialized) ----
    gemm_perm<128,64,64><<<(DK+63)/64, T, SMEM_G2>>>(ha, perm, score, W2, gm, DK);
    gather64_epi_kernel<<<(DK*32+T-1)/T, T>>>(rp2, csr2, dis2, gm, b2, t2, DK);

    // ---- conv3 (64 -> 128): gather in input space, then GEMM epi ----
    gather64_raw_kernel<<<(DK*32+T-1)/T, T>>>(rp2, csr2, dis2, t2, xa, DK);
    gemm_rt<64,128,64,true><<<(DK+63)/64, T, SMEM_G1>>>(xa, W3, b3, ha, DK);

    // ---- conv4 (128 -> 64): GEMM, then gather fused with global mean ----
    gemm_rt<128,64,64,false><<<(DK+63)/64, T, SMEM_G2>>>(ha, W4, nullptr, gm, DK);
    gather64_reduce_kernel<<<296, T>>>(rp2, csr2, dis2, gm, acc);
    write_out_kernel<<<1,64>>>(acc, b4, out);
}

// round 13
// speedup vs baseline: 1.2095x; 1.0877x over previous
#include <cuda_runtime.h>

typedef unsigned long long u64;

#define DN 50000
#define DE 800000
#define DK 40000

// ---------------- scratch layout (single __device__ blob) ----------------
static constexpr size_t OFF_XA   = 0;                               // DN*128 (gather out, reused)
static constexpr size_t OFF_HA   = OFF_XA  + (size_t)DN*128*4;      // DN*128 conv out
static constexpr size_t OFF_GM   = OFF_HA  + (size_t)DN*128*4;      // DK*64 gemm out (dis-scaled)
static constexpr size_t OFF_T2   = OFF_GM  + (size_t)DK*64*4;       // DK*64 conv2 out (dis-scaled)
static constexpr size_t OFF_XS   = OFF_T2  + (size_t)DK*64*4;       // DN*64 x*dis1
static constexpr size_t OFF_DIS1 = OFF_XS  + (size_t)DN*64*4;       // DN
static constexpr size_t OFF_DIS2 = OFF_DIS1 + (size_t)DN*4;         // DK
static constexpr size_t OFF_DEG1 = OFF_DIS2 + (size_t)DK*4;         // DN
static constexpr size_t OFF_DEG2 = OFF_DEG1 + (size_t)DN*4;         // DK
static constexpr size_t OFF_RP1  = OFF_DEG2 + (size_t)DK*4;         // DN+1
static constexpr size_t OFF_CUR1 = OFF_RP1  + (size_t)(DN+1)*4;     // DN
static constexpr size_t OFF_RP2  = OFF_CUR1 + (size_t)DN*4;         // DK+1
static constexpr size_t OFF_CUR2 = OFF_RP2  + (size_t)(DK+1)*4;     // DK
static constexpr size_t OFF_CSR1 = OFF_CUR2 + (size_t)DK*4;         // DE
static constexpr size_t OFF_CSR2 = OFF_CSR1 + (size_t)DE*4;         // DE
static constexpr size_t OFF_SCORE= OFF_CSR2 + (size_t)DE*4;         // DN
static constexpr size_t OFF_KEY  = OFF_SCORE+ (size_t)DN*4;         // DN u64
static constexpr size_t OFF_CAND = OFF_KEY  + (size_t)DN*8;         // DN u64
static constexpr size_t OFF_NEW  = OFF_CAND + (size_t)DN*8;         // DN
static constexpr size_t OFF_PERM = OFF_NEW  + (size_t)DN*4;         // DK
static constexpr size_t OFF_BINS = OFF_PERM + (size_t)DK*4;
static constexpr size_t OFF_BSUM = OFF_BINS + 256*4;                // 64
static constexpr size_t OFF_PFX  = OFF_BSUM + 64*4;
static constexpr size_t OFF_CCNT = OFF_PFX  + 8;
static constexpr size_t OFF_KCNT = OFF_CCNT + 4;
static constexpr size_t OFF_ACC  = OFF_KCNT + 4;
static constexpr size_t TOTAL_BYTES = OFF_ACC + 64*4;

__device__ __align__(256) unsigned char g_scratch[TOTAL_BYTES];

// ---------------- init ----------------
__global__ void init_kernel(int* deg1, int* deg2, int* bins, float* acc,
                            int* ccnt, int* kcnt){
    int i = blockIdx.x*blockDim.x + threadIdx.x;
    if (i < DN)  deg1[i] = 0;
    if (i < DK)  deg2[i] = 0;
    if (i < 256) bins[i] = 0;
    if (i < 64)  acc[i]  = 0.f;
    if (i == 0){ *ccnt = 0; *kcnt = 0; }
}

// ---- GEMM compute core (R12-proven): k unrolled x4, float4 broadcast x-loads
template<int KIN, int KOUT>
__device__ __forceinline__ void gemm_core(const float* sX, const float* sW,
                                          int r0, int cg,
                                          float4& a0, float4& a1, float4& a2, float4& a3){
    constexpr int CG = KOUT/4;
    const float4* w4 = (const float4*)sW;
    #pragma unroll 4
    for (int k = 0; k < KIN; k += 4){
        float4 xv0 = *(const float4*)&sX[(r0+0)*KIN + k];
        float4 xv1 = *(const float4*)&sX[(r0+1)*KIN + k];
        float4 xv2 = *(const float4*)&sX[(r0+2)*KIN + k];
        float4 xv3 = *(const float4*)&sX[(r0+3)*KIN + k];
        float4 w;
        w = w4[(k+0)*CG + cg];
        a0.x += xv0.x*w.x; a0.y += xv0.x*w.y; a0.z += xv0.x*w.z; a0.w += xv0.x*w.w;
        a1.x += xv1.x*w.x; a1.y += xv1.x*w.y; a1.z += xv1.x*w.z; a1.w += xv1.x*w.w;
        a2.x += xv2.x*w.x; a2.y += xv2.x*w.y; a2.z += xv2.x*w.z; a2.w += xv2.x*w.w;
        a3.x += xv3.x*w.x; a3.y += xv3.x*w.y; a3.z += xv3.x*w.z; a3.w += xv3.x*w.w;
        w = w4[(k+1)*CG + cg];
        a0.x += xv0.y*w.x; a0.y += xv0.y*w.y; a0.z += xv0.y*w.z; a0.w += xv0.y*w.w;
        a1.x += xv1.y*w.x; a1.y += xv1.y*w.y; a1.z += xv1.y*w.z; a1.w += xv1.y*w.w;
        a2.x += xv2.y*w.x; a2.y += xv2.y*w.y; a2.z += xv2.y*w.z; a2.w += xv2.y*w.w;
        a3.x += xv3.y*w.x; a3.y += xv3.y*w.y; a3.z += xv3.y*w.z; a3.w += xv3.y*w.w;
        w = w4[(k+2)*CG + cg];
        a0.x += xv0.z*w.x; a0.y += xv0.z*w.y; a0.z += xv0.z*w.z; a0.w += xv0.z*w.w;
        a1.x += xv1.z*w.x; a1.y += xv1.z*w.y; a1.z += xv1.z*w.z; a1.w += xv1.z*w.w;
        a2.x += xv2.z*w.x; a2.y += xv2.z*w.y; a2.z += xv2.z*w.z; a2.w += xv2.z*w.w;
        a3.x += xv3.z*w.x; a3.y += xv3.z*w.y; a3.z += xv3.z*w.z; a3.w += xv3.z*w.w;
        w = w4[(k+3)*CG + cg];
        a0.x += xv0.w*w.x; a0.y += xv0.w*w.y; a0.z += xv0.w*w.z; a0.w += xv0.w*w.w;
        a1.x += xv1.w*w.x; a1.y += xv1.w*w.y; a1.z += xv1.w*w.z; a1.w += xv1.w*w.w;
        a2.x += xv2.w*w.x; a2.y += xv2.w*w.y; a2.z += xv2.w*w.z; a2.w += xv2.w*w.w;
        a3.x += xv3.w*w.x; a3.y += xv3.w*w.y; a3.z += xv3.w*w.z; a3.w += xv3.w*w.w;
    }
}

// ---------------- register-tiled GEMM + optional bias/relu + dis-scale epi --
// EPI: Y = relu(X@W + b);  DIS: Y *= dscale[row]
template<int KIN, int KOUT, int ROWS, bool EPI, bool DIS>
__global__ void gemm_rt(const float* __restrict__ X, const float* __restrict__ W,
                        const float* __restrict__ bias, const float* __restrict__ dscale,
                        float* __restrict__ Y, int M){
    extern __shared__ float sm[];
    float* sW = sm;                 // KIN*KOUT
    float* sX = sm + KIN*KOUT;      // ROWS*KIN
    const int tid = threadIdx.x;
    constexpr int CG = KOUT/4;
    constexpr int RG = ROWS/4;
    for (int i = tid; i < KIN*KOUT/4; i += blockDim.x)
        ((float4*)sW)[i] = ((const float4*)W)[i];
    const int row0 = blockIdx.x * ROWS;
    for (int i = tid; i < ROWS*KIN/4; i += blockDim.x){
        int r  = i / (KIN/4);
        int gr = row0 + r;
        ((float4*)sX)[i] = (gr < M) ? ((const float4*)X)[(size_t)gr*(KIN/4) + (i % (KIN/4))]
                                    : make_float4(0.f,0.f,0.f,0.f);
    }
    __syncthreads();
    for (int it = tid; it < RG*CG; it += blockDim.x){
        int rg = it / CG, cg = it % CG;
        int r0 = rg*4;
        float4 a0 = make_float4(0,0,0,0), a1 = a0, a2 = a0, a3 = a0;
        gemm_core<KIN,KOUT>(sX, sW, r0, cg, a0, a1, a2, a3);
        if (EPI){
            float4 b = ((const float4*)bias)[cg];
            a0.x = fmaxf(a0.x+b.x, 0.f); a0.y = fmaxf(a0.y+b.y, 0.f);
            a0.z = fmaxf(a0.z+b.z, 0.f); a0.w = fmaxf(a0.w+b.w, 0.f);
            a1.x = fmaxf(a1.x+b.x, 0.f); a1.y = fmaxf(a1.y+b.y, 0.f);
            a1.z = fmaxf(a1.z+b.z, 0.f); a1.w = fmaxf(a1.w+b.w, 0.f);
            a2.x = fmaxf(a2.x+b.x, 0.f); a2.y = fmaxf(a2.y+b.y, 0.f);
            a2.z = fmaxf(a2.z+b.z, 0.f); a2.w = fmaxf(a2.w+b.w, 0.f);
            a3.x = fmaxf(a3.x+b.x, 0.f); a3.y = fmaxf(a3.y+b.y, 0.f);
            a3.z = fmaxf(a3.z+b.z, 0.f); a3.w = fmaxf(a3.w+b.w, 0.f);
        }
        float4* yp = (float4*)Y;
        int gr = row0 + r0;
        #pragma unroll
        for (int i = 0; i < 4; i++){
            if (gr + i < M){
                float4 v = (i==0)?a0:(i==1)?a1:(i==2)?a2:a3;
                if (DIS){
                    float d = dscale[gr+i];
                    v.x*=d; v.y*=d; v.z*=d; v.w*=d;
                }
                yp[(size_t)(gr+i)*CG + cg] = v;
            }
        }
    }
}

// ---- GEMM with permuted + score-scaled input rows, dis-scaled output -------
template<int KIN, int KOUT, int ROWS>
__global__ void gemm_perm(const float* __restrict__ X, const int* __restrict__ perm,
                          const float* __restrict__ score, const float* __restrict__ W,
                          const float* __restrict__ dscale, float* __restrict__ Y, int M){
    extern __shared__ float sm[];
    float* sW = sm;
    float* sX = sm + KIN*KOUT;
    const int tid = threadIdx.x;
    constexpr int CG = KOUT/4;
    constexpr int RG = ROWS/4;
    for (int i = tid; i < KIN*KOUT/4; i += blockDim.x)
        ((float4*)sW)[i] = ((const float4*)W)[i];
    const int row0 = blockIdx.x * ROWS;
    for (int i = tid; i < ROWS*KIN/4; i += blockDim.x){
        int r  = i / (KIN/4);
        int gr = row0 + r;
        float4 v = make_float4(0.f,0.f,0.f,0.f);
        if (gr < M){
            int on = perm[gr];
            float sc = score[on];
            v = ((const float4*)X)[(size_t)on*(KIN/4) + (i % (KIN/4))];
            v.x *= sc; v.y *= sc; v.z *= sc; v.w *= sc;
        }
        ((float4*)sX)[i] = v;
    }
    __syncthreads();
    for (int it = tid; it < RG*CG; it += blockDim.x){
        int rg = it / CG, cg = it % CG;
        int r0 = rg*4;
        float4 a0 = make_float4(0,0,0,0), a1 = a0, a2 = a0, a3 = a0;
        gemm_core<KIN,KOUT>(sX, sW, r0, cg, a0, a1, a2, a3);
        float4* yp = (float4*)Y;
        int gr = row0 + r0;
        #pragma unroll
        for (int i = 0; i < 4; i++){
            if (gr + i < M){
                float4 v = (i==0)?a0:(i==1)?a1:(i==2)?a2:a3;
                float d = dscale[gr+i];
                v.x*=d; v.y*=d; v.z*=d; v.w*=d;
                yp[(size_t)(gr+i)*CG + cg] = v;
            }
        }
    }
}

// ---------------- degree histograms ----------------
__global__ void deg_kernel(const int* __restrict__ dst, int* __restrict__ deg){
    int e = blockIdx.x*blockDim.x + threadIdx.x;
    if (e < DE) atomicAdd(&deg[dst[e]], 1);
}

__global__ void deg2_kernel(const int* __restrict__ src, const int* __restrict__ dst,
                            const int* __restrict__ nidx, int* __restrict__ deg){
    int e = blockIdx.x*blockDim.x + threadIdx.x;
    if (e >= DE) return;
    int a = nidx[src[e]];
    int b = nidx[dst[e]];
    if (a >= 0 && b >= 0) atomicAdd(&deg[b], 1);
}

// ---------------- 2-launch device-wide scan ----------------
__global__ void blocksum_kernel(const int* __restrict__ deg, int* __restrict__ bsums, int M){
    __shared__ int sh[256];
    int tid = threadIdx.x;
    int base = blockIdx.x * 1024;
    int s = 0;
    #pragma unroll
    for (int j = 0; j < 4; j++){
        int i = base + tid + j*256;
        if (i < M) s += deg[i];
    }
    sh[tid] = s;
    __syncthreads();
    for (int o = 128; o; o >>= 1){
        if (tid < o) sh[tid] += sh[tid + o];
        __syncthreads();
    }
    if (tid == 0) bsums[blockIdx.x] = sh[0];
}

__global__ void scanwrite_kernel(const int* __restrict__ deg, const int* __restrict__ bsums,
                                 int* __restrict__ rowptr, int* __restrict__ cur,
                                 float* __restrict__ dis, int M){
    __shared__ int wsum[32];
    __shared__ int base_s;
    const int tid = threadIdx.x;
    const int lane = tid & 31;
    const int wid  = tid >> 5;
    const int i = blockIdx.x*1024 + tid;
    int v = (i < M) ? deg[i] : 0;
    if (tid == 0){
        int a = 0;
        for (int j = 0; j < blockIdx.x; j++) a += bsums[j];
        base_s = a;
    }
    int s = v;
    #pragma unroll
    for (int o = 1; o < 32; o <<= 1){
        int t = __shfl_up_sync(0xffffffffu, s, o);
        if (lane >= o) s += t;
    }
    if (lane == 31) wsum[wid] = s;
    __syncthreads();
    if (wid == 0){
        int t = wsum[lane];
        #pragma unroll
        for (int o = 1; o < 32; o <<= 1){
            int u = __shfl_up_sync(0xffffffffu, t, o);
            if (lane >= o) t += u;
        }
        wsum[lane] = t;
    }
    __syncthreads();
    int woff = wid ? wsum[wid-1] : 0;
    if (i < M){
        int excl = base_s + woff + s - v;
        rowptr[i] = excl;
        cur[i]    = excl;
        dis[i]    = rsqrtf(1.0f + (float)v);
        if (i == M-1) rowptr[M] = excl + v;
    }
}

// ---------------- CSR scatter ----------------
__global__ void scatter1_kernel(const int* __restrict__ src, const int* __restrict__ dst,
                                int* __restrict__ cur, int* __restrict__ csr){
    int e = blockIdx.x*blockDim.x + threadIdx.x;
    if (e >= DE) return;
    int pos = atomicAdd(&cur[dst[e]], 1);
    csr[pos] = src[e];
}

// reads edge list + nidx directly (ns/nd never materialized)
__global__ void scatter2_kernel(const int* __restrict__ src, const int* __restrict__ dst,
                                const int* __restrict__ nidx,
                                int* __restrict__ cur, int* __restrict__ csr){
    int e = blockIdx.x*blockDim.x + threadIdx.x;
    if (e >= DE) return;
    int a = nidx[src[e]];
    if (a < 0) return;
    int b = nidx[dst[e]];
    if (b < 0) return;
    int pos = atomicAdd(&cur[b], 1);
    csr[pos] = a;
}

// ---------------- input prescale: xs = x * dis1 ----------------
__global__ void scale64_kernel(const float* __restrict__ X, const float* __restrict__ dis,
                               float* __restrict__ Y){
    int i = blockIdx.x*blockDim.x + threadIdx.x;   // float4 index
    if (i >= DN*16) return;
    float d = dis[i >> 4];
    float4 v = ((const float4*)X)[i];
    v.x*=d; v.y*=d; v.z*=d; v.w*=d;
    ((float4*)Y)[i] = v;
}

// ---------------- 64-dim CSR gathers over dis-prescaled features ------------
// SUM: out[n] = dis[n] * (G[n] + sum_s G[s])
__global__ void gather64_sum_kernel(const int* __restrict__ rowptr, const int* __restrict__ csr,
                                    const float* __restrict__ dis, const float* __restrict__ G,
                                    float* __restrict__ Hout, int M){
    int w = (blockIdx.x*blockDim.x + threadIdx.x) >> 5;
    int lane = threadIdx.x & 31;
    if (w >= M) return;
    int beg = rowptr[w], end = rowptr[w+1];
    float2 acc = ((const float2*)G)[(size_t)w*32 + lane];
    for (int j = beg; j < end; j++){
        int s = csr[j];
        float2 v = ((const float2*)G)[(size_t)s*32 + lane];
        acc.x += v.x; acc.y += v.y;
    }
    float dn = dis[w];
    acc.x *= dn; acc.y *= dn;
    ((float2*)Hout)[(size_t)w*32 + lane] = acc;
}

// EPI (conv2): out = relu(dn*acc + b) * dn   (output prescaled for conv3's gather)
__global__ void gather64_sum_epi_kernel(const int* __restrict__ rowptr, const int* __restrict__ csr,
                                        const float* __restrict__ dis, const float* __restrict__ G,
                                        const float* __restrict__ bias, float* __restrict__ Hout, int M){
    int w = (blockIdx.x*blockDim.x + threadIdx.x) >> 5;
    int lane = threadIdx.x & 31;
    if (w >= M) return;
    int beg = rowptr[w], end = rowptr[w+1];
    float2 acc = ((const float2*)G)[(size_t)w*32 + lane];
    for (int j = beg; j < end; j++){
        int s = csr[j];
        float2 v = ((const float2*)G)[(size_t)s*32 + lane];
        acc.x += v.x; acc.y += v.y;
    }
    float dn = dis[w];
    float2 b = ((const float2*)bias)[lane];
    acc.x = fmaxf(acc.x*dn + b.x, 0.f) * dn;
    acc.y = fmaxf(acc.y*dn + b.y, 0.f) * dn;
    ((float2*)Hout)[(size_t)w*32 + lane] = acc;
}

// conv4: gather + global mean accumulation (bias at writeout)
__global__ void gather64_sum_reduce_kernel(const int* __restrict__ rowptr, const int* __restrict__ csr,
                                           const float* __restrict__ dis, const float* __restrict__ G,
                                           float* __restrict__ accOut){
    __shared__ float sh[64];
    const int lane = threadIdx.x & 31;
    const int wloc = threadIdx.x >> 5;
    const int wpb  = blockDim.x >> 5;
    if (threadIdx.x < 64) sh[threadIdx.x] = 0.f;
    __syncthreads();
    int w = blockIdx.x*wpb + wloc;
    int tw = gridDim.x*wpb;
    float2 sum = make_float2(0.f, 0.f);
    for (int n = w; n < DK; n += tw){
        int beg = rowptr[n], end = rowptr[n+1];
        float2 a = ((const float2*)G)[(size_t)n*32 + lane];
        for (int j = beg; j < end; j++){
            int s = csr[j];
            float2 v = ((const float2*)G)[(size_t)s*32 + lane];
            a.x += v.x; a.y += v.y;
        }
        float dn = dis[n];
        sum.x += a.x*dn; sum.y += a.y*dn;
    }
    atomicAdd(&sh[2*lane],   sum.x);
    atomicAdd(&sh[2*lane+1], sum.y);
    __syncthreads();
    if (threadIdx.x < 64) atomicAdd(&accOut[threadIdx.x], sh[threadIdx.x]);
}

__global__ void write_out_kernel(const float* __restrict__ acc, const float* __restrict__ b4,
                                 float* __restrict__ out){
    if (threadIdx.x < 64)
        out[threadIdx.x] = acc[threadIdx.x] * (1.0f/(float)DK) + b4[threadIdx.x];
}

// ---------------- pooling: score (wnorm folded in) + radix select -----------
__global__ void score_kernel(const float* __restrict__ H, const float* __restrict__ w,
                             float* __restrict__ score, u64* __restrict__ key){
    __shared__ float swn;
    __shared__ float red[8];
    int tid = threadIdx.x;
    float q = (tid < 128) ? w[tid]*w[tid] : 0.f;
    #pragma unroll
    for (int o = 16; o; o >>= 1) q += __shfl_xor_sync(0xffffffffu, q, o);
    if ((tid & 31) == 0) red[tid >> 5] = q;
    __syncthreads();
    if (tid == 0) swn = sqrtf(red[0] + red[1] + red[2] + red[3]);
    __syncthreads();
    float wn = swn;

    int t = blockIdx.x*blockDim.x + tid;
    int n = t >> 5, lane = t & 31;
    if (n >= DN) return;
    float4 a = ((const float4*)H)[(size_t)n*32 + lane];
    float4 b = ((const float4*)w)[lane];
    float s = a.x*b.x + a.y*b.y + a.z*b.z + a.w*b.w;
    #pragma unroll
    for (int o = 16; o; o >>= 1) s += __shfl_xor_sync(0xffffffffu, s, o);
    if (lane == 0){
        s = tanhf(s / wn);
        score[n] = s;
        unsigned ub = __float_as_uint(s);
        ub = (ub & 0x80000000u) ? ~ub : (ub | 0x80000000u);   // order-preserving map
        key[n] = ((u64)ub << 32) | (u64)(0xffffffffu - (unsigned)n);  // distinct keys
    }
}

__global__ void hist_kernel(const u64* __restrict__ key, int* __restrict__ bins){
    __shared__ int sb[256];
    if (threadIdx.x < 256) sb[threadIdx.x] = 0;
    __syncthreads();
    for (int n = blockIdx.x*blockDim.x + threadIdx.x; n < DN; n += gridDim.x*blockDim.x)
        atomicAdd(&sb[(int)(key[n] >> 56)], 1);
    __syncthreads();
    if (threadIdx.x < 256 && sb[threadIdx.x]) atomicAdd(&bins[threadIdx.x], sb[threadIdx.x]);
}

__global__ void compact_kernel(const u64* __restrict__ key, const int* __restrict__ bins,
                               u64* __restrict__ cand, int* __restrict__ cnt){
    __shared__ int s_top;
    if (threadIdx.x == 0){
        int rem = DK;
        int bb = 0;
        for (int b = 255; b >= 0; b--){
            int c = bins[b];
            if (rem <= c){ bb = b; break; }
            rem -= c;
        }
        s_top = bb;
    }
    __syncthreads();
    u64 top = (u64)s_top;
    int n = blockIdx.x*blockDim.x + threadIdx.x;
    if (n >= DN) return;
    u64 k = key[n];
    if ((k >> 56) == top){
        int p = atomicAdd(cnt, 1);
        cand[p] = k;
    }
}

__global__ void finish_select_kernel(const u64* __restrict__ cand, const int* __restrict__ cntp,
                                     const int* __restrict__ gbins, u64* __restrict__ pfxp){
    __shared__ int bins[256];
    __shared__ u64 s_pfx;
    __shared__ int s_rem;
    const int tid = threadIdx.x;
    const int C = *cntp;
    if (tid == 0){
        int rem = DK;
        int bb = 0;
        for (int b = 255; b >= 0; b--){
            int c = gbins[b];
            if (rem <= c){ bb = b; break; }
            rem -= c;
        }
        s_pfx = ((u64)bb) << 56;
        s_rem = rem;
    }
    __syncthreads();
    for (int shift = 48; shift >= 0; shift -= 8){
        if (tid < 256) bins[tid] = 0;
        __syncthreads();
        u64 pfx = s_pfx;
        for (int i = tid; i < C; i += blockDim.x){
            u64 k = cand[i];
            if ((k >> (shift+8)) == (pfx >> (shift+8)))
                atomicAdd(&bins[(int)((k >> shift) & 0xFF)], 1);
        }
        __syncthreads();
        if (tid == 0){
            int rem = s_rem;
            for (int b = 255; b >= 0; b--){
                int c = bins[b];
                if (rem <= c){ s_pfx = pfx | (((u64)b) << shift); break; }
                rem -= c;
            }
            s_rem = rem;
        }
        __syncthreads();
    }
    if (tid == 0) *pfxp = s_pfx;
}

// ---------------- kept-node labeling (order-free; output is label-invariant) -
__global__ void newidx_atomic_kernel(const u64* __restrict__ key, const u64* __restrict__ pfxp,
                                     int* __restrict__ cnt, int* __restrict__ nidx,
                                     int* __restrict__ perm){
    int n = blockIdx.x*blockDim.x + threadIdx.x;
    if (n >= DN) return;
    u64 pfx = *pfxp;
    if (key[n] >= pfx){
        int p = atomicAdd(cnt, 1);
        nidx[n] = p;
        perm[p] = n;
    } else {
        nidx[n] = -1;
    }
}

// ---------------- launch ----------------
extern "C" void kernel_launch(void* const* d_in, const int* in_sizes, int n_in,
                              void* d_out, int out_size){
    const float* x   = (const float*)d_in[0];
    const int*   ei  = (const int*)  d_in[1];
    const int*   src = ei;
    const int*   dst = ei + DE;
    const float* W1  = (const float*)d_in[3];
    const float* b1  = (const float*)d_in[4];
    const float* pw  = (const float*)d_in[5];
    const float* W2  = (const float*)d_in[6];
    const float* b2  = (const float*)d_in[7];
    const float* W3  = (const float*)d_in[8];
    const float* b3  = (const float*)d_in[9];
    const float* W4  = (const float*)d_in[10];
    const float* b4  = (const float*)d_in[11];
    float* out = (float*)d_out;

    void* basep = nullptr;
    cudaGetSymbolAddress(&basep, g_scratch);
    unsigned char* B = (unsigned char*)basep;
    float* xa    = (float*)(B + OFF_XA);
    float* ha    = (float*)(B + OFF_HA);
    float* gm    = (float*)(B + OFF_GM);
    float* t2    = (float*)(B + OFF_T2);
    float* xs    = (float*)(B + OFF_XS);
    float* dis1  = (float*)(B + OFF_DIS1);
    float* dis2  = (float*)(B + OFF_DIS2);
    int*   deg1  = (int*)  (B + OFF_DEG1);
    int*   deg2  = (int*)  (B + OFF_DEG2);
    int*   rp1   = (int*)  (B + OFF_RP1);
    int*   cur1  = (int*)  (B + OFF_CUR1);
    int*   rp2   = (int*)  (B + OFF_RP2);
    int*   cur2  = (int*)  (B + OFF_CUR2);
    int*   csr1  = (int*)  (B + OFF_CSR1);
    int*   csr2  = (int*)  (B + OFF_CSR2);
    float* score = (float*)(B + OFF_SCORE);
    u64*   key   = (u64*)  (B + OFF_KEY);
    u64*   cand  = (u64*)  (B + OFF_CAND);
    int*   nidx  = (int*)  (B + OFF_NEW);
    int*   perm  = (int*)  (B + OFF_PERM);
    int*   bins  = (int*)  (B + OFF_BINS);
    int*   bsum  = (int*)  (B + OFF_BSUM);
    u64*   pfx   = (u64*)  (B + OFF_PFX);
    int*   ccnt  = (int*)  (B + OFF_CCNT);
    int*   kcnt  = (int*)  (B + OFF_KCNT);
    float* acc   = (float*)(B + OFF_ACC);

    const int T = 256;
    const int NB1 = (DN + 1023)/1024;   // 49
    const int NB2 = (DK + 1023)/1024;   // 40
    const int SMEM_G1 = (64*128 + 64*64)*4;    // 48 KB (KIN=64, KOUT=128, ROWS=64)
    const int SMEM_G2 = (128*64 + 64*128)*4;   // 64 KB (KIN=128, KOUT=64, ROWS=64)
    cudaFuncSetAttribute(gemm_rt<128,64,64,false,true>, cudaFuncAttributeMaxDynamicSharedMemorySize, SMEM_G2);
    cudaFuncSetAttribute(gemm_perm<128,64,64>,          cudaFuncAttributeMaxDynamicSharedMemorySize, SMEM_G2);

    // reset all per-replay state
    init_kernel<<<(DN+T-1)/T, T>>>(deg1, deg2, bins, acc, ccnt, kcnt);

    // ---- CSR for the full graph ----
    deg_kernel<<<(DE+T-1)/T, T>>>(dst, deg1);
    blocksum_kernel<<<NB1, 256>>>(deg1, bsum, DN);
    scanwrite_kernel<<<NB1, 1024>>>(deg1, bsum, rp1, cur1, dis1, DN);
    scatter1_kernel<<<(DE+T-1)/T, T>>>(src, dst, cur1, csr1);

    // ---- conv1: prescale x, pure-sum gather, GEMM(+bias+relu) ----
    scale64_kernel<<<(DN*16+T-1)/T, T>>>(x, dis1, xs);
    gather64_sum_kernel<<<(DN*32+T-1)/T, T>>>(rp1, csr1, dis1, xs, xa, DN);
    gemm_rt<64,128,64,true,false><<<(DN+63)/64, T, SMEM_G1>>>(xa, W1, b1, nullptr, ha, DN);

    // ---- TopK pooling (exact radix select) ----
    score_kernel<<<(DN*32+T-1)/T, T>>>(ha, pw, score, key);
    hist_kernel<<<128, T>>>(key, bins);
    compact_kernel<<<(DN+T-1)/T, T>>>(key, bins, cand, ccnt);
    finish_select_kernel<<<1, 1024>>>(cand, ccnt, bins, pfx);
    newidx_atomic_kernel<<<(DN+T-1)/T, T>>>(key, pfx, kcnt, nidx, perm);

    // ---- pooled-graph CSR (ns/nd never materialized) ----
    deg2_kernel<<<(DE+T-1)/T, T>>>(src, dst, nidx, deg2);
    blocksum_kernel<<<NB2, 256>>>(deg2, bsum, DK);
    scanwrite_kernel<<<NB2, 1024>>>(deg2, bsum, rp2, cur2, dis2, DK);
    scatter2_kernel<<<(DE+T-1)/T, T>>>(src, dst, nidx, cur2, csr2);

    // ---- conv2 (128 -> 64): perm-indirect GEMM (output ×dis2), sum-gather epi
    gemm_perm<128,64,64><<<(DK+63)/64, T, SMEM_G2>>>(ha, perm, score, W2, dis2, gm, DK);
    gather64_sum_epi_kernel<<<(DK*32+T-1)/T, T>>>(rp2, csr2, dis2, gm, b2, t2, DK);

    // ---- conv3 (64 -> 128): t2 already dis-prescaled; sum-gather then GEMM epi
    gather64_sum_kernel<<<(DK*32+T-1)/T, T>>>(rp2, csr2, dis2, t2, xa, DK);
    gemm_rt<64,128,64,true,false><<<(DK+63)/64, T, SMEM_G1>>>(xa, W3, b3, nullptr, ha, DK);

    // ---- conv4 (128 -> 64): GEMM (output ×dis2), gather fused with global mean
    gemm_rt<128,64,64,false,true><<<(DK+63)/64, T, SMEM_G2>>>(ha, W4, nullptr, dis2, gm, DK);
    gather64_sum_reduce_kernel<<<296, T>>>(rp2, csr2, dis2, gm, acc);
    write_out_kernel<<<1,64>>>(acc, b4, out);
}

// round 14
// speedup vs baseline: 1.2325x; 1.0190x over previous
#include <cuda_runtime.h>

typedef unsigned long long u64;

#define DN 50000
#define DE 800000
#define DK 40000

// ---------------- scratch layout (single __device__ blob) ----------------
static constexpr size_t OFF_XA   = 0;                               // DN*128 (gather out, reused)
static constexpr size_t OFF_HA   = OFF_XA  + (size_t)DN*128*4;      // DN*128 conv out
static constexpr size_t OFF_GM   = OFF_HA  + (size_t)DN*128*4;      // DK*64 gemm out (dis-scaled)
static constexpr size_t OFF_T2   = OFF_GM  + (size_t)DK*64*4;       // DK*64 conv2 out (dis-scaled)
static constexpr size_t OFF_XS   = OFF_T2  + (size_t)DK*64*4;       // DN*64 x*dis1
static constexpr size_t OFF_DIS1 = OFF_XS  + (size_t)DN*64*4;       // DN
static constexpr size_t OFF_DIS2 = OFF_DIS1 + (size_t)DN*4;         // DK
static constexpr size_t OFF_DEG1 = OFF_DIS2 + (size_t)DK*4;         // DN
static constexpr size_t OFF_DEG2 = OFF_DEG1 + (size_t)DN*4;         // DK
static constexpr size_t OFF_RP1  = OFF_DEG2 + (size_t)DK*4;         // DN+1
static constexpr size_t OFF_CUR1 = OFF_RP1  + (size_t)(DN+1)*4;     // DN
static constexpr size_t OFF_RP2  = OFF_CUR1 + (size_t)DN*4;         // DK+1
static constexpr size_t OFF_CUR2 = OFF_RP2  + (size_t)(DK+1)*4;     // DK
static constexpr size_t OFF_CSR1 = OFF_CUR2 + (size_t)DK*4;         // DE
static constexpr size_t OFF_CSR2 = OFF_CSR1 + (size_t)DE*4;         // DE
static constexpr size_t OFF_SCORE= OFF_CSR2 + (size_t)DE*4;         // DN
static constexpr size_t OFF_KEY  = OFF_SCORE+ (size_t)DN*4;         // DN u64
static constexpr size_t OFF_CAND = OFF_KEY  + (size_t)DN*8;         // DN u64
static constexpr size_t OFF_NEW  = OFF_CAND + (size_t)DN*8;         // DN
static constexpr size_t OFF_PERM = OFF_NEW  + (size_t)DN*4;         // DK
static constexpr size_t OFF_BINS = OFF_PERM + (size_t)DK*4;
static constexpr size_t OFF_BSUM = OFF_BINS + 256*4;                // 64
static constexpr size_t OFF_PFX  = OFF_BSUM + 64*4;
static constexpr size_t OFF_CCNT = OFF_PFX  + 8;
static constexpr size_t OFF_KCNT = OFF_CCNT + 4;
static constexpr size_t OFF_ACC  = OFF_KCNT + 4;
static constexpr size_t TOTAL_BYTES = OFF_ACC + 64*4;

__device__ __align__(256) unsigned char g_scratch[TOTAL_BYTES];

// ---------------- init ----------------
__global__ void init_kernel(int* deg1, int* deg2, int* bins, float* acc,
                            int* ccnt, int* kcnt){
    int i = blockIdx.x*blockDim.x + threadIdx.x;
    if (i < DN)  deg1[i] = 0;
    if (i < DK)  deg2[i] = 0;
    if (i < 256) bins[i] = 0;
    if (i < 64)  acc[i]  = 0.f;
    if (i == 0){ *ccnt = 0; *kcnt = 0; }
}

// ---------------- packed f32x2 helpers ----------------
__device__ __forceinline__ u64 pack2(float v){
    u64 r; asm("mov.b64 %0, {%1, %1};" : "=l"(r) : "f"(v)); return r;
}
__device__ __forceinline__ void ffma2(u64& d, u64 a, u64 b){
    asm("fma.rn.f32x2 %0, %1, %2, %0;" : "+l"(d) : "l"(a), "l"(b));
}
__device__ __forceinline__ float2 unpack2(u64 v){
    float2 f; asm("mov.b64 {%0, %1}, %2;" : "=f"(f.x), "=f"(f.y) : "l"(v)); return f;
}

// ---- GEMM compute core: k unrolled x4, float4 broadcast x-loads, FFMA2 -----
// acc[8]: row i -> acc[2i] = cols(x,y), acc[2i+1] = cols(z,w)
template<int KIN, int KOUT>
__device__ __forceinline__ void gemm_core2(const float* sX, const float* sW,
                                           int r0, int cg, u64* acc){
    constexpr int CG = KOUT/4;
    #pragma unroll 4
    for (int k = 0; k < KIN; k += 4){
        float4 xv0 = *(const float4*)&sX[(r0+0)*KIN + k];
        float4 xv1 = *(const float4*)&sX[(r0+1)*KIN + k];
        float4 xv2 = *(const float4*)&sX[(r0+2)*KIN + k];
        float4 xv3 = *(const float4*)&sX[(r0+3)*KIN + k];
        {
            ulonglong2 w = *(const ulonglong2*)&sW[(size_t)(k+0)*KOUT + cg*4];
            u64 p0 = pack2(xv0.x), p1 = pack2(xv1.x), p2 = pack2(xv2.x), p3 = pack2(xv3.x);
            ffma2(acc[0], p0, w.x); ffma2(acc[1], p0, w.y);
            ffma2(acc[2], p1, w.x); ffma2(acc[3], p1, w.y);
            ffma2(acc[4], p2, w.x); ffma2(acc[5], p2, w.y);
            ffma2(acc[6], p3, w.x); ffma2(acc[7], p3, w.y);
        }
        {
            ulonglong2 w = *(const ulonglong2*)&sW[(size_t)(k+1)*KOUT + cg*4];
            u64 p0 = pack2(xv0.y), p1 = pack2(xv1.y), p2 = pack2(xv2.y), p3 = pack2(xv3.y);
            ffma2(acc[0], p0, w.x); ffma2(acc[1], p0, w.y);
            ffma2(acc[2], p1, w.x); ffma2(acc[3], p1, w.y);
            ffma2(acc[4], p2, w.x); ffma2(acc[5], p2, w.y);
            ffma2(acc[6], p3, w.x); ffma2(acc[7], p3, w.y);
        }
        {
            ulonglong2 w = *(const ulonglong2*)&sW[(size_t)(k+2)*KOUT + cg*4];
            u64 p0 = pack2(xv0.z), p1 = pack2(xv1.z), p2 = pack2(xv2.z), p3 = pack2(xv3.z);
            ffma2(acc[0], p0, w.x); ffma2(acc[1], p0, w.y);
            ffma2(acc[2], p1, w.x); ffma2(acc[3], p1, w.y);
            ffma2(acc[4], p2, w.x); ffma2(acc[5], p2, w.y);
            ffma2(acc[6], p3, w.x); ffma2(acc[7], p3, w.y);
        }
        {
            ulonglong2 w = *(const ulonglong2*)&sW[(size_t)(k+3)*KOUT + cg*4];
            u64 p0 = pack2(xv0.w), p1 = pack2(xv1.w), p2 = pack2(xv2.w), p3 = pack2(xv3.w);
            ffma2(acc[0], p0, w.x); ffma2(acc[1], p0, w.y);
            ffma2(acc[2], p1, w.x); ffma2(acc[3], p1, w.y);
            ffma2(acc[4], p2, w.x); ffma2(acc[5], p2, w.y);
            ffma2(acc[6], p3, w.x); ffma2(acc[7], p3, w.y);
        }
    }
}

__device__ __forceinline__ float4 acc_to_f4(u64 lo, u64 hi){
    float2 l = unpack2(lo), h = unpack2(hi);
    return make_float4(l.x, l.y, h.x, h.y);
}

// ---------------- register-tiled GEMM + optional bias/relu + dis-scale epi --
template<int KIN, int KOUT, int ROWS, bool EPI, bool DIS>
__global__ void gemm_rt(const float* __restrict__ X, const float* __restrict__ W,
                        const float* __restrict__ bias, const float* __restrict__ dscale,
                        float* __restrict__ Y, int M){
    extern __shared__ float sm[];
    float* sW = sm;                 // KIN*KOUT
    float* sX = sm + KIN*KOUT;      // ROWS*KIN
    const int tid = threadIdx.x;
    constexpr int CG = KOUT/4;
    constexpr int RG = ROWS/4;
    for (int i = tid; i < KIN*KOUT/4; i += blockDim.x)
        ((float4*)sW)[i] = ((const float4*)W)[i];
    const int row0 = blockIdx.x * ROWS;
    for (int i = tid; i < ROWS*KIN/4; i += blockDim.x){
        int r  = i / (KIN/4);
        int gr = row0 + r;
        ((float4*)sX)[i] = (gr < M) ? ((const float4*)X)[(size_t)gr*(KIN/4) + (i % (KIN/4))]
                                    : make_float4(0.f,0.f,0.f,0.f);
    }
    __syncthreads();
    for (int it = tid; it < RG*CG; it += blockDim.x){
        int rg = it / CG, cg = it % CG;
        int r0 = rg*4;
        u64 acc[8] = {0,0,0,0,0,0,0,0};
        gemm_core2<KIN,KOUT>(sX, sW, r0, cg, acc);
        float4* yp = (float4*)Y;
        int gr = row0 + r0;
        float4 b;
        if (EPI) b = ((const float4*)bias)[cg];
        #pragma unroll
        for (int i = 0; i < 4; i++){
            if (gr + i < M){
                float4 v = acc_to_f4(acc[2*i], acc[2*i+1]);
                if (EPI){
                    v.x = fmaxf(v.x+b.x, 0.f); v.y = fmaxf(v.y+b.y, 0.f);
                    v.z = fmaxf(v.z+b.z, 0.f); v.w = fmaxf(v.w+b.w, 0.f);
                }
                if (DIS){
                    float d = dscale[gr+i];
                    v.x*=d; v.y*=d; v.z*=d; v.w*=d;
                }
                yp[(size_t)(gr+i)*CG + cg] = v;
            }
        }
    }
}

// ---- GEMM with permuted + score-scaled input rows, dis-scaled output -------
template<int KIN, int KOUT, int ROWS>
__global__ void gemm_perm(const float* __restrict__ X, const int* __restrict__ perm,
                          const float* __restrict__ score, const float* __restrict__ W,
                          const float* __restrict__ dscale, float* __restrict__ Y, int M){
    extern __shared__ float sm[];
    float* sW = sm;
    float* sX = sm + KIN*KOUT;
    const int tid = threadIdx.x;
    constexpr int CG = KOUT/4;
    constexpr int RG = ROWS/4;
    for (int i = tid; i < KIN*KOUT/4; i += blockDim.x)
        ((float4*)sW)[i] = ((const float4*)W)[i];
    const int row0 = blockIdx.x * ROWS;
    for (int i = tid; i < ROWS*KIN/4; i += blockDim.x){
        int r  = i / (KIN/4);
        int gr = row0 + r;
        float4 v = make_float4(0.f,0.f,0.f,0.f);
        if (gr < M){
            int on = perm[gr];
            float sc = score[on];
            v = ((const float4*)X)[(size_t)on*(KIN/4) + (i % (KIN/4))];
            v.x *= sc; v.y *= sc; v.z *= sc; v.w *= sc;
        }
        ((float4*)sX)[i] = v;
    }
    __syncthreads();
    for (int it = tid; it < RG*CG; it += blockDim.x){
        int rg = it / CG, cg = it % CG;
        int r0 = rg*4;
        u64 acc[8] = {0,0,0,0,0,0,0,0};
        gemm_core2<KIN,KOUT>(sX, sW, r0, cg, acc);
        float4* yp = (float4*)Y;
        int gr = row0 + r0;
        #pragma unroll
        for (int i = 0; i < 4; i++){
            if (gr + i < M){
                float4 v = acc_to_f4(acc[2*i], acc[2*i+1]);
                float d = dscale[gr+i];
                v.x*=d; v.y*=d; v.z*=d; v.w*=d;
                yp[(size_t)(gr+i)*CG + cg] = v;
            }
        }
    }
}

// ---------------- degree histograms ----------------
__global__ void deg_kernel(const int* __restrict__ dst, int* __restrict__ deg){
    int e = blockIdx.x*blockDim.x + threadIdx.x;
    if (e < DE) atomicAdd(&deg[dst[e]], 1);
}

__global__ void deg2_kernel(const int* __restrict__ src, const int* __restrict__ dst,
                            const int* __restrict__ nidx, int* __restrict__ deg){
    int e = blockIdx.x*blockDim.x + threadIdx.x;
    if (e >= DE) return;
    int a = nidx[src[e]];
    int b = nidx[dst[e]];
    if (a >= 0 && b >= 0) atomicAdd(&deg[b], 1);
}

// ---------------- 2-launch device-wide scan ----------------
__global__ void blocksum_kernel(const int* __restrict__ deg, int* __restrict__ bsums, int M){
    __shared__ int sh[256];
    int tid = threadIdx.x;
    int base = blockIdx.x * 1024;
    int s = 0;
    #pragma unroll
    for (int j = 0; j < 4; j++){
        int i = base + tid + j*256;
        if (i < M) s += deg[i];
    }
    sh[tid] = s;
    __syncthreads();
    for (int o = 128; o; o >>= 1){
        if (tid < o) sh[tid] += sh[tid + o];
        __syncthreads();
    }
    if (tid == 0) bsums[blockIdx.x] = sh[0];
}

__global__ void scanwrite_kernel(const int* __restrict__ deg, const int* __restrict__ bsums,
                                 int* __restrict__ rowptr, int* __restrict__ cur,
                                 float* __restrict__ dis, int M){
    __shared__ int wsum[32];
    __shared__ int base_s;
    const int tid = threadIdx.x;
    const int lane = tid & 31;
    const int wid  = tid >> 5;
    const int i = blockIdx.x*1024 + tid;
    int v = (i < M) ? deg[i] : 0;
    if (tid == 0){
        int a = 0;
        for (int j = 0; j < blockIdx.x; j++) a += bsums[j];
        base_s = a;
    }
    int s = v;
    #pragma unroll
    for (int o = 1; o < 32; o <<= 1){
        int t = __shfl_up_sync(0xffffffffu, s, o);
        if (lane >= o) s += t;
    }
    if (lane == 31) wsum[wid] = s;
    __syncthreads();
    if (wid == 0){
        int t = wsum[lane];
        #pragma unroll
        for (int o = 1; o < 32; o <<= 1){
            int u = __shfl_up_sync(0xffffffffu, t, o);
            if (lane >= o) t += u;
        }
        wsum[lane] = t;
    }
    __syncthreads();
    int woff = wid ? wsum[wid-1] : 0;
    if (i < M){
        int excl = base_s + woff + s - v;
        rowptr[i] = excl;
        cur[i]    = excl;
        dis[i]    = rsqrtf(1.0f + (float)v);
        if (i == M-1) rowptr[M] = excl + v;
    }
}

// ---------------- CSR scatter ----------------
__global__ void scatter1_kernel(const int* __restrict__ src, const int* __restrict__ dst,
                                int* __restrict__ cur, int* __restrict__ csr){
    int e = blockIdx.x*blockDim.x + threadIdx.x;
    if (e >= DE) return;
    int pos = atomicAdd(&cur[dst[e]], 1);
    csr[pos] = src[e];
}

__global__ void scatter2_kernel(const int* __restrict__ src, const int* __restrict__ dst,
                                const int* __restrict__ nidx,
                                int* __restrict__ cur, int* __restrict__ csr){
    int e = blockIdx.x*blockDim.x + threadIdx.x;
    if (e >= DE) return;
    int a = nidx[src[e]];
    if (a < 0) return;
    int b = nidx[dst[e]];
    if (b < 0) return;
    int pos = atomicAdd(&cur[b], 1);
    csr[pos] = a;
}

// ---------------- input prescale: xs = x * dis1 ----------------
__global__ void scale64_kernel(const float* __restrict__ X, const float* __restrict__ dis,
                               float* __restrict__ Y){
    int i = blockIdx.x*blockDim.x + threadIdx.x;   // float4 index
    if (i >= DN*16) return;
    float d = dis[i >> 4];
    float4 v = ((const float4*)X)[i];
    v.x*=d; v.y*=d; v.z*=d; v.w*=d;
    ((float4*)Y)[i] = v;
}

// ---------------- 64-dim CSR gathers over dis-prescaled features ------------
__global__ void gather64_sum_kernel(const int* __restrict__ rowptr, const int* __restrict__ csr,
                                    const float* __restrict__ dis, const float* __restrict__ G,
                                    float* __restrict__ Hout, int M){
    int w = (blockIdx.x*blockDim.x + threadIdx.x) >> 5;
    int lane = threadIdx.x & 31;
    if (w >= M) return;
    int beg = rowptr[w], end = rowptr[w+1];
    float2 acc = ((const float2*)G)[(size_t)w*32 + lane];
    for (int j = beg; j < end; j++){
        int s = csr[j];
        float2 v = ((const float2*)G)[(size_t)s*32 + lane];
        acc.x += v.x; acc.y += v.y;
    }
    float dn = dis[w];
    acc.x *= dn; acc.y *= dn;
    ((float2*)Hout)[(size_t)w*32 + lane] = acc;
}

__global__ void gather64_sum_epi_kernel(const int* __restrict__ rowptr, const int* __restrict__ csr,
                                        const float* __restrict__ dis, const float* __restrict__ G,
                                        const float* __restrict__ bias, float* __restrict__ Hout, int M){
    int w = (blockIdx.x*blockDim.x + threadIdx.x) >> 5;
    int lane = threadIdx.x & 31;
    if (w >= M) return;
    int beg = rowptr[w], end = rowptr[w+1];
    float2 acc = ((const float2*)G)[(size_t)w*32 + lane];
    for (int j = beg; j < end; j++){
        int s = csr[j];
        float2 v = ((const float2*)G)[(size_t)s*32 + lane];
        acc.x += v.x; acc.y += v.y;
    }
    float dn = dis[w];
    float2 b = ((const float2*)bias)[lane];
    acc.x = fmaxf(acc.x*dn + b.x, 0.f) * dn;
    acc.y = fmaxf(acc.y*dn + b.y, 0.f) * dn;
    ((float2*)Hout)[(size_t)w*32 + lane] = acc;
}

__global__ void gather64_sum_reduce_kernel(const int* __restrict__ rowptr, const int* __restrict__ csr,
                                           const float* __restrict__ dis, const float* __restrict__ G,
                                           float* __restrict__ accOut){
    __shared__ float sh[64];
    const int lane = threadIdx.x & 31;
    const int wloc = threadIdx.x >> 5;
    const int wpb  = blockDim.x >> 5;
    if (threadIdx.x < 64) sh[threadIdx.x] = 0.f;
    __syncthreads();
    int w = blockIdx.x*wpb + wloc;
    int tw = gridDim.x*wpb;
    float2 sum = make_float2(0.f, 0.f);
    for (int n = w; n < DK; n += tw){
        int beg = rowptr[n], end = rowptr[n+1];
        float2 a = ((const float2*)G)[(size_t)n*32 + lane];
        for (int j = beg; j < end; j++){
            int s = csr[j];
            float2 v = ((const float2*)G)[(size_t)s*32 + lane];
            a.x += v.x; a.y += v.y;
        }
        float dn = dis[n];
        sum.x += a.x*dn; sum.y += a.y*dn;
    }
    atomicAdd(&sh[2*lane],   sum.x);
    atomicAdd(&sh[2*lane+1], sum.y);
    __syncthreads();
    if (threadIdx.x < 64) atomicAdd(&accOut[threadIdx.x], sh[threadIdx.x]);
}

__global__ void write_out_kernel(const float* __restrict__ acc, const float* __restrict__ b4,
                                 float* __restrict__ out){
    if (threadIdx.x < 64)
        out[threadIdx.x] = acc[threadIdx.x] * (1.0f/(float)DK) + b4[threadIdx.x];
}

// ---------------- pooling: score (wnorm folded in) + radix select -----------
__global__ void score_kernel(const float* __restrict__ H, const float* __restrict__ w,
                             float* __restrict__ score, u64* __restrict__ key){
    __shared__ float swn;
    __shared__ float red[8];
    int tid = threadIdx.x;
    float q = (tid < 128) ? w[tid]*w[tid] : 0.f;
    #pragma unroll
    for (int o = 16; o; o >>= 1) q += __shfl_xor_sync(0xffffffffu, q, o);
    if ((tid & 31) == 0) red[tid >> 5] = q;
    __syncthreads();
    if (tid == 0) swn = sqrtf(red[0] + red[1] + red[2] + red[3]);
    __syncthreads();
    float wn = swn;

    int t = blockIdx.x*blockDim.x + tid;
    int n = t >> 5, lane = t & 31;
    if (n >= DN) return;
    float4 a = ((const float4*)H)[(size_t)n*32 + lane];
    float4 b = ((const float4*)w)[lane];
    float s = a.x*b.x + a.y*b.y + a.z*b.z + a.w*b.w;
    #pragma unroll
    for (int o = 16; o; o >>= 1) s += __shfl_xor_sync(0xffffffffu, s, o);
    if (lane == 0){
        s = tanhf(s / wn);
        score[n] = s;
        unsigned ub = __float_as_uint(s);
        ub = (ub & 0x80000000u) ? ~ub : (ub | 0x80000000u);   // order-preserving map
        key[n] = ((u64)ub << 32) | (u64)(0xffffffffu - (unsigned)n);  // distinct keys
    }
}

__global__ void hist_kernel(const u64* __restrict__ key, int* __restrict__ bins){
    __shared__ int sb[256];
    if (threadIdx.x < 256) sb[threadIdx.x] = 0;
    __syncthreads();
    for (int n = blockIdx.x*blockDim.x + threadIdx.x; n < DN; n += gridDim.x*blockDim.x)
        atomicAdd(&sb[(int)(key[n] >> 56)], 1);
    __syncthreads();
    if (threadIdx.x < 256 && sb[threadIdx.x]) atomicAdd(&bins[threadIdx.x], sb[threadIdx.x]);
}

__global__ void compact_kernel(const u64* __restrict__ key, const int* __restrict__ bins,
                               u64* __restrict__ cand, int* __restrict__ cnt){
    __shared__ int s_top;
    if (threadIdx.x == 0){
        int rem = DK;
        int bb = 0;
        for (int b = 255; b >= 0; b--){
            int c = bins[b];
            if (rem <= c){ bb = b; break; }
            rem -= c;
        }
        s_top = bb;
    }
    __syncthreads();
    u64 top = (u64)s_top;
    int n = blockIdx.x*blockDim.x + threadIdx.x;
    if (n >= DN) return;
    u64 k = key[n];
    if ((k >> 56) == top){
        int p = atomicAdd(cnt, 1);
        cand[p] = k;
    }
}

__global__ void finish_select_kernel(const u64* __restrict__ cand, const int* __restrict__ cntp,
                                     const int* __restrict__ gbins, u64* __restrict__ pfxp){
    __shared__ int bins[256];
    __shared__ u64 s_pfx;
    __shared__ int s_rem;
    const int tid = threadIdx.x;
    const int C = *cntp;
    if (tid == 0){
        int rem = DK;
        int bb = 0;
        for (int b = 255; b >= 0; b--){
            int c = gbins[b];
            if (rem <= c){ bb = b; break; }
            rem -= c;
        }
        s_pfx = ((u64)bb) << 56;
        s_rem = rem;
    }
    __syncthreads();
    for (int shift = 48; shift >= 0; shift -= 8){
        if (tid < 256) bins[tid] = 0;
        __syncthreads();
        u64 pfx = s_pfx;
        for (int i = tid; i < C; i += blockDim.x){
            u64 k = cand[i];
            if ((k >> (shift+8)) == (pfx >> (shift+8)))
                atomicAdd(&bins[(int)((k >> shift) & 0xFF)], 1);
        }
        __syncthreads();
        if (tid == 0){
            int rem = s_rem;
            for (int b = 255; b >= 0; b--){
                int c = bins[b];
                if (rem <= c){ s_pfx = pfx | (((u64)b) << shift); break; }
                rem -= c;
            }
            s_rem = rem;
        }
        __syncthreads();
    }
    if (tid == 0) *pfxp = s_pfx;
}

// ---------------- kept-node labeling (order-free; output is label-invariant) -
__global__ void newidx_atomic_kernel(const u64* __restrict__ key, const u64* __restrict__ pfxp,
                                     int* __restrict__ cnt, int* __restrict__ nidx,
                                     int* __restrict__ perm){
    int n = blockIdx.x*blockDim.x + threadIdx.x;
    if (n >= DN) return;
    u64 pfx = *pfxp;
    if (key[n] >= pfx){
        int p = atomicAdd(cnt, 1);
        nidx[n] = p;
        perm[p] = n;
    } else {
        nidx[n] = -1;
    }
}

// ---------------- launch ----------------
extern "C" void kernel_launch(void* const* d_in, const int* in_sizes, int n_in,
                              void* d_out, int out_size){
    const float* x   = (const float*)d_in[0];
    const int*   ei  = (const int*)  d_in[1];
    const int*   src = ei;
    const int*   dst = ei + DE;
    const float* W1  = (const float*)d_in[3];
    const float* b1  = (const float*)d_in[4];
    const float* pw  = (const float*)d_in[5];
    const float* W2  = (const float*)d_in[6];
    const float* b2  = (const float*)d_in[7];
    const float* W3  = (const float*)d_in[8];
    const float* b3  = (const float*)d_in[9];
    const float* W4  = (const float*)d_in[10];
    const float* b4  = (const float*)d_in[11];
    float* out = (float*)d_out;

    void* basep = nullptr;
    cudaGetSymbolAddress(&basep, g_scratch);
    unsigned char* B = (unsigned char*)basep;
    float* xa    = (float*)(B + OFF_XA);
    float* ha    = (float*)(B + OFF_HA);
    float* gm    = (float*)(B + OFF_GM);
    float* t2    = (float*)(B + OFF_T2);
    float* xs    = (float*)(B + OFF_XS);
    float* dis1  = (float*)(B + OFF_DIS1);
    float* dis2  = (float*)(B + OFF_DIS2);
    int*   deg1  = (int*)  (B + OFF_DEG1);
    int*   deg2  = (int*)  (B + OFF_DEG2);
    int*   rp1   = (int*)  (B + OFF_RP1);
    int*   cur1  = (int*)  (B + OFF_CUR1);
    int*   rp2   = (int*)  (B + OFF_RP2);
    int*   cur2  = (int*)  (B + OFF_CUR2);
    int*   csr1  = (int*)  (B + OFF_CSR1);
    int*   csr2  = (int*)  (B + OFF_CSR2);
    float* score = (float*)(B + OFF_SCORE);
    u64*   key   = (u64*)  (B + OFF_KEY);
    u64*   cand  = (u64*)  (B + OFF_CAND);
    int*   nidx  = (int*)  (B + OFF_NEW);
    int*   perm  = (int*)  (B + OFF_PERM);
    int*   bins  = (int*)  (B + OFF_BINS);
    int*   bsum  = (int*)  (B + OFF_BSUM);
    u64*   pfx   = (u64*)  (B + OFF_PFX);
    int*   ccnt  = (int*)  (B + OFF_CCNT);
    int*   kcnt  = (int*)  (B + OFF_KCNT);
    float* acc   = (float*)(B + OFF_ACC);

    const int T = 256;
    const int NB1 = (DN + 1023)/1024;   // 49
    const int NB2 = (DK + 1023)/1024;   // 40
    const int SMEM_G1 = (64*128 + 64*64)*4;    // 48 KB (KIN=64, KOUT=128, ROWS=64)
    const int SMEM_G2 = (128*64 + 64*128)*4;   // 64 KB (KIN=128, KOUT=64, ROWS=64)
    cudaFuncSetAttribute(gemm_rt<128,64,64,false,true>, cudaFuncAttributeMaxDynamicSharedMemorySize, SMEM_G2);
    cudaFuncSetAttribute(gemm_perm<128,64,64>,          cudaFuncAttributeMaxDynamicSharedMemorySize, SMEM_G2);

    // reset all per-replay state
    init_kernel<<<(DN+T-1)/T, T>>>(deg1, deg2, bins, acc, ccnt, kcnt);

    // ---- CSR for the full graph ----
    deg_kernel<<<(DE+T-1)/T, T>>>(dst, deg1);
    blocksum_kernel<<<NB1, 256>>>(deg1, bsum, DN);
    scanwrite_kernel<<<NB1, 1024>>>(deg1, bsum, rp1, cur1, dis1, DN);
    scatter1_kernel<<<(DE+T-1)/T, T>>>(src, dst, cur1, csr1);

    // ---- conv1: prescale x, pure-sum gather, GEMM(+bias+relu) ----
    scale64_kernel<<<(DN*16+T-1)/T, T>>>(x, dis1, xs);
    gather64_sum_kernel<<<(DN*32+T-1)/T, T>>>(rp1, csr1, dis1, xs, xa, DN);
    gemm_rt<64,128,64,true,false><<<(DN+63)/64, T, SMEM_G1>>>(xa, W1, b1, nullptr, ha, DN);

    // ---- TopK pooling (exact radix select) ----
    score_kernel<<<(DN*32+T-1)/T, T>>>(ha, pw, score, key);
    hist_kernel<<<128, T>>>(key, bins);
    compact_kernel<<<(DN+T-1)/T, T>>>(key, bins, cand, ccnt);
    finish_select_kernel<<<1, 1024>>>(cand, ccnt, bins, pfx);
    newidx_atomic_kernel<<<(DN+T-1)/T, T>>>(key, pfx, kcnt, nidx, perm);

    // ---- pooled-graph CSR (ns/nd never materialized) ----
    deg2_kernel<<<(DE+T-1)/T, T>>>(src, dst, nidx, deg2);
    blocksum_kernel<<<NB2, 256>>>(deg2, bsum, DK);
    scanwrite_kernel<<<NB2, 1024>>>(deg2, bsum, rp2, cur2, dis2, DK);
    scatter2_kernel<<<(DE+T-1)/T, T>>>(src, dst, nidx, cur2, csr2);

    // ---- conv2 (128 -> 64): perm-indirect GEMM (output ×dis2), sum-gather epi
    gemm_perm<128,64,64><<<(DK+63)/64, T, SMEM_G2>>>(ha, perm, score, W2, dis2, gm, DK);
    gather64_sum_epi_kernel<<<(DK*32+T-1)/T, T>>>(rp2, csr2, dis2, gm, b2, t2, DK);

    // ---- conv3 (64 -> 128): t2 already dis-prescaled; sum-gather then GEMM epi
    gather64_sum_kernel<<<(DK*32+T-1)/T, T>>>(rp2, csr2, dis2, t2, xa, DK);
    gemm_rt<64,128,64,true,false><<<(DK+63)/64, T, SMEM_G1>>>(xa, W3, b3, nullptr, ha, DK);

    // ---- conv4 (128 -> 64): GEMM (output ×dis2), gather fused with global mean
    gemm_rt<128,64,64,false,true><<<(DK+63)/64, T, SMEM_G2>>>(ha, W4, nullptr, dis2, gm, DK);
    gather64_sum_reduce_kernel<<<296, T>>>(rp2, csr2, dis2, gm, acc);
    write_out_kernel<<<1,64>>>(acc, b4, out);
}